// round 9
// baseline (speedup 1.0000x reference)
#include <cuda_runtime.h>
#include <cuda_bf16.h>

#define DINL __device__ __forceinline__

// ---------------------------------------------------------------------------
// Packed f32x2 helpers (Blackwell FFMA2 path)
// ---------------------------------------------------------------------------
typedef unsigned long long u64;

DINL u64 ffma2u(u64 a, u64 b, u64 c) {
    u64 d;
    asm("fma.rn.f32x2 %0, %1, %2, %3;" : "=l"(d) : "l"(a), "l"(b), "l"(c));
    return d;
}
DINL u64 add2(u64 a, u64 b) {
    u64 d;
    asm("add.rn.f32x2 %0, %1, %2;" : "=l"(d) : "l"(a), "l"(b));
    return d;
}
DINL u64 pack2(float a, float b) {
    u64 u; asm("mov.b64 %0, {%1, %2};" : "=l"(u) : "f"(a), "f"(b)); return u;
}
DINL u64 packdup(float a) {
    u64 u; asm("mov.b64 %0, {%1, %1};" : "=l"(u) : "f"(a)); return u;
}
DINL float2 unpk(u64 u) {
    float2 v; asm("mov.b64 {%0, %1}, %2;" : "=f"(v.x), "=f"(v.y) : "l"(u)); return v;
}
DINL float sig_(float x)  { return __fdividef(1.f, 1.f + __expf(-x)); }
DINL float tanh_(float x) { return __fdividef(2.f, 1.f + __expf(-2.f * x)) - 1.f; }

// ---------------------------------------------------------------------------
// Device-global scratch (no allocation allowed)
// ---------------------------------------------------------------------------
__device__ float4 d_WT4_e1[32 * 512];    // Whh_e1 transposed: [k4][g] float4 over k
__device__ float  d_bias_e1[512];        // bih_e1 + bhh_e1
__device__ float4 d_WT4_d1[32 * 512];    // Whh_d1 transposed
__device__ float  d_bias_d1[512];
__device__ float  d_WihT_e2[128 * 256];  // Wih_e2 transposed [k][g]
__device__ float  d_bias_e2[256];
__device__ float  d_h1[4096 * 128];      // e1 final hidden per batch element
__device__ float  d_pre2[4096 * 256];    // e2 input proj + bias, K3-permuted layout
__device__ float  d_zvec[64];            // e2 final hidden

// K3 thread mapping: tid in [0,128): w = tid>>5, l = tid&31,
//   j = w*16 + (l&15), q2 = l>>4.
//   q2==0 -> rows (j, 128+j)  = gates (i, g)
//   q2==1 -> rows (64+j, 192+j) = gates (f, o)
// pre2 slot for gate-row r: q=r>>6, j=r&63; q2=q&1; slot=q>>1;
//   tid = (j>>4)*32 + (q2<<4) + (j&15); addr = t*256 + tid*2 + slot.

// ---------------------------------------------------------------------------
// K0: weight transposes / bias folding
// ---------------------------------------------------------------------------
__global__ void k0_prep(const float* __restrict__ Whh_e1,
                        const float* __restrict__ bih_e1, const float* __restrict__ bhh_e1,
                        const float* __restrict__ Wih_e2,
                        const float* __restrict__ bih_e2, const float* __restrict__ bhh_e2,
                        const float* __restrict__ Whh_d1,
                        const float* __restrict__ bih_d1, const float* __restrict__ bhh_d1) {
    int stride = gridDim.x * blockDim.x;
    int tid0 = blockIdx.x * blockDim.x + threadIdx.x;
    for (int i = tid0; i < 32 * 512; i += stride) {
        int k4 = i >> 9, g = i & 511;
        const float* r1 = Whh_e1 + g * 128 + 4 * k4;
        d_WT4_e1[i] = make_float4(r1[0], r1[1], r1[2], r1[3]);
        const float* r2 = Whh_d1 + g * 128 + 4 * k4;
        d_WT4_d1[i] = make_float4(r2[0], r2[1], r2[2], r2[3]);
    }
    for (int i = tid0; i < 512; i += stride) {
        d_bias_e1[i] = bih_e1[i] + bhh_e1[i];
        d_bias_d1[i] = bih_d1[i] + bhh_d1[i];
    }
    for (int i = tid0; i < 128 * 256; i += stride) {
        int k = i >> 8, g = i & 255;
        d_WihT_e2[i] = Wih_e2[g * 128 + k];
    }
    for (int i = tid0; i < 256; i += stride) d_bias_e2[i] = bih_e2[i] + bhh_e2[i];
}

// ---------------------------------------------------------------------------
// K1: encoder LSTM 1.  147 blocks x 512 threads, 28 batch elems per block.
// Thread g owns gate row g for all 28 elems; h broadcast from SMEM; FFMA2
// over batch pairs; weights streamed coalesced (float4 transposed layout).
// c lives in SMEM (frees 28 regs/thread); c/h update distributed 512-wide.
// ---------------------------------------------------------------------------
#define K1_NB 28
__global__ __launch_bounds__(512, 1) void k1_e1(const float* __restrict__ x,
                                                const float* __restrict__ Wih_e1) {
    extern __shared__ float sm[];
    float* xs   = sm;                       // [28][140]
    float* hs   = sm + K1_NB * 140;         // [128][30]
    float* gsh  = hs + 128 * 30;            // [512][29]
    float* c_sh = gsh + 512 * 29;           // [28][128]
    const int g = threadIdx.x;
    const int base = blockIdx.x * K1_NB;
    int nb = 4096 - base; if (nb > K1_NB) nb = K1_NB;

    for (int i = g; i < K1_NB * 140; i += 512) {
        int b = i / 140, tt = i - b * 140;
        xs[i] = (b < nb) ? x[(base + b) * 140 + tt] : 0.f;
    }
    for (int i = g; i < 128 * 30; i += 512) hs[i] = 0.f;
    for (int i = g; i < K1_NB * 128; i += 512) c_sh[i] = 0.f;

    const float wih  = Wih_e1[g];
    const float bias = d_bias_e1[g];
    const bool  is_t = (g >= 256 && g < 384);   // tanh for the 'g' gate
    const float4* __restrict__ Wp = d_WT4_e1 + g;
    const u64* hs2 = (const u64*)hs;
    __syncthreads();

    for (int t = 0; t < 140; ++t) {
        u64 acc[14];
#pragma unroll
        for (int bp = 0; bp < 14; ++bp) {
            acc[bp] = pack2(fmaf(wih, xs[(2 * bp) * 140 + t], bias),
                            fmaf(wih, xs[(2 * bp + 1) * 140 + t], bias));
        }
#pragma unroll 4
        for (int k4 = 0; k4 < 32; ++k4) {
            float4 w = Wp[(size_t)k4 * 512];
            const u64* hk = hs2 + (4 * k4) * 15;
            u64 wd;
            wd = packdup(w.x);
#pragma unroll
            for (int bp = 0; bp < 14; ++bp) acc[bp] = ffma2u(wd, hk[bp], acc[bp]);
            wd = packdup(w.y);
#pragma unroll
            for (int bp = 0; bp < 14; ++bp) acc[bp] = ffma2u(wd, hk[15 + bp], acc[bp]);
            wd = packdup(w.z);
#pragma unroll
            for (int bp = 0; bp < 14; ++bp) acc[bp] = ffma2u(wd, hk[30 + bp], acc[bp]);
            wd = packdup(w.w);
#pragma unroll
            for (int bp = 0; bp < 14; ++bp) acc[bp] = ffma2u(wd, hk[45 + bp], acc[bp]);
        }
#pragma unroll
        for (int bp = 0; bp < 14; ++bp) {
            float2 v = unpk(acc[bp]);
            float a0 = is_t ? tanh_(v.x) : sig_(v.x);
            float a1 = is_t ? tanh_(v.y) : sig_(v.y);
            gsh[g * 29 + 2 * bp]     = a0;
            gsh[g * 29 + 2 * bp + 1] = a1;
        }
        __syncthreads();
        // distributed c/h update: 3584 (j,b) pairs over 512 threads
#pragma unroll
        for (int i = 0; i < 7; ++i) {
            int idx = g + 512 * i;
            int j = idx & 127, b = idx >> 7;
            float iv = gsh[j * 29 + b];
            float fv = gsh[(128 + j) * 29 + b];
            float gv = gsh[(256 + j) * 29 + b];
            float ov = gsh[(384 + j) * 29 + b];
            float cc = fmaf(fv, c_sh[b * 128 + j], iv * gv);
            c_sh[b * 128 + j] = cc;
            hs[j * 30 + b] = ov * tanh_(cc);
        }
        __syncthreads();
    }
    if (g < 128) {
        for (int b = 0; b < nb; ++b) d_h1[(base + b) * 128 + g] = hs[g * 30 + b];
    }
}
#define K1_SMEM ((K1_NB * 140 + 128 * 30 + 512 * 29 + K1_NB * 128) * 4)

// ---------------------------------------------------------------------------
// K2: e2 input projection into K3-permuted layout
// ---------------------------------------------------------------------------
__global__ __launch_bounds__(256, 1) void k2_proj() {
    __shared__ float hsm[32 * 128];
    const int g = threadIdx.x;        // gate row 0..255
    const int t0 = blockIdx.x * 32;
    for (int i = g; i < 32 * 128; i += 256) hsm[i] = d_h1[t0 * 128 + i];
    __syncthreads();
    float acc[32];
#pragma unroll
    for (int r = 0; r < 32; ++r) acc[r] = 0.f;
    for (int k = 0; k < 128; ++k) {
        float w = d_WihT_e2[k * 256 + g];
#pragma unroll
        for (int r = 0; r < 32; ++r) acc[r] = fmaf(hsm[r * 128 + k], w, acc[r]);
    }
    float b = d_bias_e2[g];
    // permuted destination
    int q = g >> 6, j = g & 63;
    int q2 = q & 1, slot = q >> 1;
    int tid2 = (j >> 4) * 32 + (q2 << 4) + (j & 15);
    int dst = tid2 * 2 + slot;
#pragma unroll
    for (int r = 0; r < 32; ++r) d_pre2[(t0 + r) * 256 + dst] = acc[r] + b;
}

// ---------------------------------------------------------------------------
// K3: e2 serial scan. 1 block, 128 threads, 4096 steps, H=64.
// Thread (j,q2) owns 2 gate rows (weights in regs), gate exchange via
// shfl_xor(16) within the warp, h ping-pong in SMEM, ONE bar per step.
// ---------------------------------------------------------------------------
__global__ __launch_bounds__(128, 1) void k3_e2(const float* __restrict__ Whh_e2) {
    __shared__ float h_sh[2][64];
    const int tid = threadIdx.x;
    const int w = tid >> 5, l = tid & 31;
    const int j = w * 16 + (l & 15);
    const int q2 = l >> 4;
    const int r0 = q2 ? (64 + j) : j;
    const int r1 = q2 ? (192 + j) : (128 + j);

    u64 w0[32], w1[32];
    const u64* W2 = (const u64*)Whh_e2;
#pragma unroll
    for (int k = 0; k < 32; ++k) { w0[k] = W2[r0 * 32 + k]; w1[k] = W2[r1 * 32 + k]; }

    if (tid < 64) h_sh[0][tid] = 0.f;
    float c = 0.f;
    u64 pre_cur = ((const u64*)d_pre2)[tid];   // (pre_r0, pre_r1) at t=0
    __syncthreads();

    for (int t = 0; t < 4096; ++t) {
        u64 pre_nxt = (t < 4095) ? ((const u64*)d_pre2)[(t + 1) * 128 + tid] : 0ull;
        const u64* hp = (const u64*)h_sh[t & 1 ? 1 : 0];
        u64 a00 = 0, a01 = 0, a10 = 0, a11 = 0;
#pragma unroll
        for (int k = 0; k < 32; k += 2) {
            u64 h0 = hp[k], h1 = hp[k + 1];
            a00 = ffma2u(w0[k],     h0, a00);
            a01 = ffma2u(w0[k + 1], h1, a01);
            a10 = ffma2u(w1[k],     h0, a10);
            a11 = ffma2u(w1[k + 1], h1, a11);
        }
        a00 = add2(a00, a01);
        a10 = add2(a10, a11);
        float2 v0 = unpk(a00), v1 = unpk(a10);
        float2 pc = unpk(pre_cur);
        float s0 = v0.x + v0.y + pc.x;
        float s1 = v1.x + v1.y + pc.y;
        // q2==0: (i, g) ; q2==1: (f, o)
        float act0 = sig_(s0);
        float act1 = q2 ? sig_(s1) : tanh_(s1);
        float o0 = __shfl_xor_sync(0xffffffffu, act0, 16);
        float o1 = __shfl_xor_sync(0xffffffffu, act1, 16);
        float iv = q2 ? o0 : act0;
        float fv = q2 ? act0 : o0;
        float gv = q2 ? o1 : act1;
        float ov = q2 ? act1 : o1;
        c = fmaf(fv, c, iv * gv);
        float h = ov * tanh_(c);
        if (q2 == 0) h_sh[(t & 1) ^ 1][j] = h;
        __syncthreads();
        pre_cur = pre_nxt;
    }
    // 4096 steps: last write went to buffer 0
    if (tid < 64) d_zvec[tid] = h_sh[0][tid];
}

// ---------------------------------------------------------------------------
// K4: decoder (d1 H=128 + fused d2 H=1). 1 block, 512 threads, 140 steps.
// ---------------------------------------------------------------------------
__global__ __launch_bounds__(512, 1) void k4_dec(const float* __restrict__ Wih_d1,
                                                 const float* __restrict__ Wih_d2,
                                                 const float* __restrict__ Whh_d2,
                                                 const float* __restrict__ bih_d2,
                                                 const float* __restrict__ bhh_d2,
                                                 float* __restrict__ out) {
    __shared__ float zsh[64];
    __shared__ float h_sh[128];
    __shared__ float gsh[512];
    const int g = threadIdx.x;
    if (g < 64)  zsh[g] = d_zvec[g];
    if (g < 128) h_sh[g] = 0.f;
    __syncthreads();
    float wz = d_bias_d1[g];
#pragma unroll 8
    for (int k = 0; k < 64; ++k) wz = fmaf(Wih_d1[g * 64 + k], zsh[k], wz);
    const bool is_t = (g >= 256 && g < 384);
    float c = 0.f;

    // warp-0 d2 state
    float wd2[16], b2[4], wh[4];
    float c2 = 0.f, h2 = 0.f;
    if (g < 32) {
#pragma unroll
        for (int q = 0; q < 4; ++q) {
#pragma unroll
            for (int m = 0; m < 4; ++m) wd2[q * 4 + m] = Wih_d2[q * 128 + m * 32 + g];
            b2[q] = bih_d2[q] + bhh_d2[q];
            wh[q] = Whh_d2[q];
        }
    }
    const float4* __restrict__ Wp = d_WT4_d1 + g;
    const u64* hs2 = (const u64*)h_sh;

    for (int t = 0; t < 140; ++t) {
        u64 a0 = 0, a1 = 0;
#pragma unroll 8
        for (int k4 = 0; k4 < 32; ++k4) {
            float4 w = Wp[(size_t)k4 * 512];
            a0 = ffma2u(pack2(w.x, w.y), hs2[2 * k4], a0);
            a1 = ffma2u(pack2(w.z, w.w), hs2[2 * k4 + 1], a1);
        }
        a0 = add2(a0, a1);
        float2 v = unpk(a0);
        float xv = v.x + v.y + wz;
        gsh[g] = is_t ? tanh_(xv) : sig_(xv);
        __syncthreads();
        if (g < 128) {
            float iv = gsh[g], fv = gsh[128 + g], gv = gsh[256 + g], ov = gsh[384 + g];
            c = fmaf(fv, c, iv * gv);
            h_sh[g] = ov * tanh_(c);
        }
        __syncthreads();
        if (g < 32) {
            float p0 = 0.f, p1 = 0.f, p2 = 0.f, p3 = 0.f;
#pragma unroll
            for (int m = 0; m < 4; ++m) {
                float hv = h_sh[m * 32 + g];
                p0 = fmaf(wd2[0 * 4 + m], hv, p0);
                p1 = fmaf(wd2[1 * 4 + m], hv, p1);
                p2 = fmaf(wd2[2 * 4 + m], hv, p2);
                p3 = fmaf(wd2[3 * 4 + m], hv, p3);
            }
#pragma unroll
            for (int off = 16; off > 0; off >>= 1) {
                p0 += __shfl_xor_sync(0xffffffffu, p0, off);
                p1 += __shfl_xor_sync(0xffffffffu, p1, off);
                p2 += __shfl_xor_sync(0xffffffffu, p2, off);
                p3 += __shfl_xor_sync(0xffffffffu, p3, off);
            }
            float iv2 = sig_(p0 + b2[0] + wh[0] * h2);
            float fv2 = sig_(p1 + b2[1] + wh[1] * h2);
            float gv2 = tanh_(p2 + b2[2] + wh[2] * h2);
            float ov2 = sig_(p3 + b2[3] + wh[3] * h2);
            c2 = fmaf(fv2, c2, iv2 * gv2);
            h2 = ov2 * tanh_(c2);
            if (g == 0) out[t] = h2;
        }
    }
}

// ---------------------------------------------------------------------------
// Launch
// ---------------------------------------------------------------------------
extern "C" void kernel_launch(void* const* d_in, const int* in_sizes, int n_in,
                              void* d_out, int out_size) {
    const float* x      = (const float*)d_in[0];
    const float* Wih_e1 = (const float*)d_in[1];
    const float* Whh_e1 = (const float*)d_in[2];
    const float* bih_e1 = (const float*)d_in[3];
    const float* bhh_e1 = (const float*)d_in[4];
    const float* Wih_e2 = (const float*)d_in[5];
    const float* Whh_e2 = (const float*)d_in[6];
    const float* bih_e2 = (const float*)d_in[7];
    const float* bhh_e2 = (const float*)d_in[8];
    const float* Wih_d1 = (const float*)d_in[9];
    const float* Whh_d1 = (const float*)d_in[10];
    const float* bih_d1 = (const float*)d_in[11];
    const float* bhh_d1 = (const float*)d_in[12];
    const float* Wih_d2 = (const float*)d_in[13];
    const float* Whh_d2 = (const float*)d_in[14];
    const float* bih_d2 = (const float*)d_in[15];
    const float* bhh_d2 = (const float*)d_in[16];
    float* out = (float*)d_out;
    (void)in_sizes; (void)n_in; (void)out_size;

    cudaFuncSetAttribute(k1_e1, cudaFuncAttributeMaxDynamicSharedMemorySize, K1_SMEM);

    k0_prep<<<64, 256>>>(Whh_e1, bih_e1, bhh_e1, Wih_e2, bih_e2, bhh_e2,
                         Whh_d1, bih_d1, bhh_d1);
    k1_e1<<<147, 512, K1_SMEM>>>(x, Wih_e1);
    k2_proj<<<128, 256>>>();
    k3_e2<<<1, 128>>>(Whh_e2);
    k4_dec<<<1, 512>>>(Wih_d1, Wih_d2, Whh_d2, bih_d2, bhh_d2, out);
}

// round 10
// speedup vs baseline: 1.3146x; 1.3146x over previous
#include <cuda_runtime.h>
#include <cuda_bf16.h>

#define DINL __device__ __forceinline__
typedef unsigned long long u64;
typedef unsigned int u32;

// ---------------------------------------------------------------------------
// helpers
// ---------------------------------------------------------------------------
DINL u64 ffma2u(u64 a, u64 b, u64 c) {
    u64 d;
    asm("fma.rn.f32x2 %0, %1, %2, %3;" : "=l"(d) : "l"(a), "l"(b), "l"(c));
    return d;
}
DINL u64 add2(u64 a, u64 b) {
    u64 d;
    asm("add.rn.f32x2 %0, %1, %2;" : "=l"(d) : "l"(a), "l"(b));
    return d;
}
DINL u64 pack2(float a, float b) {
    u64 u; asm("mov.b64 %0, {%1, %2};" : "=l"(u) : "f"(a), "f"(b)); return u;
}
DINL float2 unpk(u64 u) {
    float2 v; asm("mov.b64 {%0, %1}, %2;" : "=f"(v.x), "=f"(v.y) : "l"(u)); return v;
}
DINL float tanha(float x) {
    float r; asm("tanh.approx.f32 %0, %1;" : "=f"(r) : "f"(x)); return r;
}
DINL float sigm(float x) { return fmaf(tanha(0.5f * x), 0.5f, 0.5f); }
DINL u32 cvt_tf32(float x) {
    u32 r; asm("cvt.rna.tf32.f32 %0, %1;" : "=r"(r) : "f"(x)); return r;
}
DINL float tf32f(float x) { return __uint_as_float(cvt_tf32(x)); }

DINL void mma1688(float& c0, float& c1, float& c2, float& c3,
                  u32 a0, u32 a1, u32 a2, u32 a3, u32 b0, u32 b1) {
    asm("mma.sync.aligned.m16n8k8.row.col.f32.tf32.tf32.f32 "
        "{%0,%1,%2,%3}, {%4,%5,%6,%7}, {%8,%9}, {%0,%1,%2,%3};"
        : "+f"(c0), "+f"(c1), "+f"(c2), "+f"(c3)
        : "r"(a0), "r"(a1), "r"(a2), "r"(a3), "r"(b0), "r"(b1));
}

// ---------------------------------------------------------------------------
// Device-global scratch
// ---------------------------------------------------------------------------
__device__ float4 d_WA_e1[32 * 16 * 32]; // Whh_e1 as tf32 mma A-fragments [mt][kt][lane]
__device__ float  d_bias_e1[512];
__device__ float4 d_WT4_d1[32 * 512];    // Whh_d1 transposed
__device__ float  d_bias_d1[512];
__device__ float  d_WihT_e2[128 * 256];  // Wih_e2 transposed [k][g]
__device__ float  d_bias_e2[256];
__device__ float  d_h1[4096 * 128];
__device__ float  d_pre2[4096 * 256];    // K3-permuted layout
__device__ float  d_zvec[64];

// ---------------------------------------------------------------------------
// K0: weight packing / bias folding
// ---------------------------------------------------------------------------
__global__ void k0_prep(const float* __restrict__ Whh_e1,
                        const float* __restrict__ bih_e1, const float* __restrict__ bhh_e1,
                        const float* __restrict__ Wih_e2,
                        const float* __restrict__ bih_e2, const float* __restrict__ bhh_e2,
                        const float* __restrict__ Whh_d1,
                        const float* __restrict__ bih_d1, const float* __restrict__ bhh_d1) {
    int stride = gridDim.x * blockDim.x;
    int tid0 = blockIdx.x * blockDim.x + threadIdx.x;
    // Whh_e1 -> tf32 A fragments: a0=(g,tg) a1=(g+8,tg) a2=(g,tg+4) a3=(g+8,tg+4)
    for (int idx = tid0; idx < 32 * 16 * 32; idx += stride) {
        int lane = idx & 31, kt = (idx >> 5) & 15, mt = idx >> 9;
        int g = lane >> 2, tg = lane & 3;
        int r0 = mt * 16 + g, r1 = r0 + 8;
        int c0 = kt * 8 + tg, c1 = c0 + 4;
        d_WA_e1[idx] = make_float4(tf32f(Whh_e1[r0 * 128 + c0]),
                                   tf32f(Whh_e1[r1 * 128 + c0]),
                                   tf32f(Whh_e1[r0 * 128 + c1]),
                                   tf32f(Whh_e1[r1 * 128 + c1]));
    }
    for (int i = tid0; i < 32 * 512; i += stride) {
        int k4 = i >> 9, g = i & 511;
        const float* r2 = Whh_d1 + g * 128 + 4 * k4;
        d_WT4_d1[i] = make_float4(r2[0], r2[1], r2[2], r2[3]);
    }
    for (int i = tid0; i < 512; i += stride) {
        d_bias_e1[i] = bih_e1[i] + bhh_e1[i];
        d_bias_d1[i] = bih_d1[i] + bhh_d1[i];
    }
    for (int i = tid0; i < 128 * 256; i += stride) {
        int k = i >> 8, g = i & 255;
        d_WihT_e2[i] = Wih_e2[g * 128 + k];
    }
    for (int i = tid0; i < 256; i += stride) d_bias_e2[i] = bih_e2[i] + bhh_e2[i];
}

// ---------------------------------------------------------------------------
// K1: encoder LSTM 1 on tensor cores (tf32 mma.sync m16n8k8).
// 64 blocks x 512 threads, 64 batch elems per block.
// gates[512,64] = Whh[512,128] @ h[128,64] via HMMA; warp w owns Mtiles {w,w+16}:
//   w<8  -> (i, g~) rows;  w>=8 -> (f, o) rows at identical fragment positions.
// Epilogue exchanges only f,o through SMEM; c in SMEM; h stored as tf32.
// ---------------------------------------------------------------------------
#define NB1 64
#define XS_STR 66
#define H_STR  68
#define FO_STR 66
#define SM_X   (140 * XS_STR)
#define SM_H   (128 * H_STR)
#define SM_FO  (128 * FO_STR)
#define K1_FLOATS (SM_X + 2 * SM_H + 2 * SM_FO + SM_FO)
#define K1_SMEM (K1_FLOATS * 4)

__global__ __launch_bounds__(512, 1) void k1_e1(const float* __restrict__ x,
                                                const float* __restrict__ Wih_e1) {
    extern __shared__ float sm[];
    float* xs = sm;                    // [140][66]  x transposed: xs[t][b]
    float* hA = xs + SM_X;             // [128][68]  h buf0 (tf32 values)
    float* hB = hA + SM_H;             // h buf1
    float* fo = hB + SM_H;             // [2][128][66]  f and o exchange
    float* cs = fo + 2 * SM_FO;        // [128][66]  cell state

    const int tid = threadIdx.x;
    const int w = tid >> 5, lane = tid & 31;
    const int g = lane >> 2, tg = lane & 3;
    const int base = blockIdx.x * NB1;

    // load x transposed (coalesced along t)
    for (int i = tid; i < NB1 * 140; i += 512) {
        int b = i / 140, t = i - b * 140;
        xs[t * XS_STR + b] = x[(base + b) * 140 + t];
    }
    for (int i = tid; i < SM_H; i += 512) hA[i] = 0.f;
    for (int i = tid; i < SM_FO; i += 512) cs[i] = 0.f;

    // per-thread row constants (4 gate rows)
    const int mt0 = w, mt1 = w + 16;
    const int r00 = mt0 * 16 + g, r01 = r00 + 8;
    const int r10 = mt1 * 16 + g, r11 = r10 + 8;
    const float wi0 = Wih_e1[r00], wi1 = Wih_e1[r01];
    const float wi2 = Wih_e1[r10], wi3 = Wih_e1[r11];
    const float bb0 = d_bias_e1[r00], bb1 = d_bias_e1[r01];
    const float bb2 = d_bias_e1[r10], bb3 = d_bias_e1[r11];
    const int jb = (w < 8) ? (w * 16 + g) : ((w - 8) * 16 + g);   // local hidden row
    __syncthreads();

    const float4* __restrict__ WAlo = d_WA_e1 + mt0 * 16 * 32 + lane;
    const float4* __restrict__ WAhi = d_WA_e1 + mt1 * 16 * 32 + lane;

    float* hcur = hA;
    float* hnext = hB;

    for (int t = 0; t < 140; ++t) {
        float C0[8][4], C1[8][4];
        // init: bias + Wih * x_t
#pragma unroll
        for (int nt = 0; nt < 8; ++nt) {
            float2 xp = *(const float2*)&xs[t * XS_STR + nt * 8 + 2 * tg];
            C0[nt][0] = fmaf(wi0, xp.x, bb0); C0[nt][1] = fmaf(wi0, xp.y, bb0);
            C0[nt][2] = fmaf(wi1, xp.x, bb1); C0[nt][3] = fmaf(wi1, xp.y, bb1);
            C1[nt][0] = fmaf(wi2, xp.x, bb2); C1[nt][1] = fmaf(wi2, xp.y, bb2);
            C1[nt][2] = fmaf(wi3, xp.x, bb3); C1[nt][3] = fmaf(wi3, xp.y, bb3);
        }
        // mma over K tiles
#pragma unroll 2
        for (int kt = 0; kt < 16; ++kt) {
            float4 wlo = WAlo[kt * 32];
            float4 whi = WAhi[kt * 32];
            u32 al0 = __float_as_uint(wlo.x), al1 = __float_as_uint(wlo.y);
            u32 al2 = __float_as_uint(wlo.z), al3 = __float_as_uint(wlo.w);
            u32 ah0 = __float_as_uint(whi.x), ah1 = __float_as_uint(whi.y);
            u32 ah2 = __float_as_uint(whi.z), ah3 = __float_as_uint(whi.w);
            const float* hk = hcur + (kt * 8 + tg) * H_STR;
#pragma unroll
            for (int nt = 0; nt < 8; ++nt) {
                u32 b0 = __float_as_uint(hk[nt * 8 + g]);
                u32 b1 = __float_as_uint(hk[4 * H_STR + nt * 8 + g]);
                mma1688(C0[nt][0], C0[nt][1], C0[nt][2], C0[nt][3],
                        al0, al1, al2, al3, b0, b1);
                mma1688(C1[nt][0], C1[nt][1], C1[nt][2], C1[nt][3],
                        ah0, ah1, ah2, ah3, b0, b1);
            }
        }
        // activations
        if (w >= 8) {
            // f (C0) and o (C1): activate and store to fo
#pragma unroll
            for (int nt = 0; nt < 8; ++nt) {
                int bc = nt * 8 + 2 * tg;
                float2 f0 = make_float2(sigm(C0[nt][0]), sigm(C0[nt][1]));
                float2 f1 = make_float2(sigm(C0[nt][2]), sigm(C0[nt][3]));
                float2 o0 = make_float2(sigm(C1[nt][0]), sigm(C1[nt][1]));
                float2 o1 = make_float2(sigm(C1[nt][2]), sigm(C1[nt][3]));
                *(float2*)&fo[jb * FO_STR + bc] = f0;
                *(float2*)&fo[(jb + 8) * FO_STR + bc] = f1;
                *(float2*)&fo[SM_FO + jb * FO_STR + bc] = o0;
                *(float2*)&fo[SM_FO + (jb + 8) * FO_STR + bc] = o1;
            }
        } else {
            // i (C0) and g~ (C1): activate in place
#pragma unroll
            for (int nt = 0; nt < 8; ++nt) {
                C0[nt][0] = sigm(C0[nt][0]); C0[nt][1] = sigm(C0[nt][1]);
                C0[nt][2] = sigm(C0[nt][2]); C0[nt][3] = sigm(C0[nt][3]);
                C1[nt][0] = tanha(C1[nt][0]); C1[nt][1] = tanha(C1[nt][1]);
                C1[nt][2] = tanha(C1[nt][2]); C1[nt][3] = tanha(C1[nt][3]);
            }
        }
        __syncthreads();
        if (w < 8) {
#pragma unroll
            for (int nt = 0; nt < 8; ++nt) {
                int bc = nt * 8 + 2 * tg;
                float2 fp0 = *(const float2*)&fo[jb * FO_STR + bc];
                float2 fp1 = *(const float2*)&fo[(jb + 8) * FO_STR + bc];
                float2 op0 = *(const float2*)&fo[SM_FO + jb * FO_STR + bc];
                float2 op1 = *(const float2*)&fo[SM_FO + (jb + 8) * FO_STR + bc];
                float2 cp0 = *(const float2*)&cs[jb * FO_STR + bc];
                float2 cp1 = *(const float2*)&cs[(jb + 8) * FO_STR + bc];
                cp0.x = fmaf(fp0.x, cp0.x, C0[nt][0] * C1[nt][0]);
                cp0.y = fmaf(fp0.y, cp0.y, C0[nt][1] * C1[nt][1]);
                cp1.x = fmaf(fp1.x, cp1.x, C0[nt][2] * C1[nt][2]);
                cp1.y = fmaf(fp1.y, cp1.y, C0[nt][3] * C1[nt][3]);
                *(float2*)&cs[jb * FO_STR + bc] = cp0;
                *(float2*)&cs[(jb + 8) * FO_STR + bc] = cp1;
                float2 h0 = make_float2(tf32f(op0.x * tanha(cp0.x)),
                                        tf32f(op0.y * tanha(cp0.y)));
                float2 h1 = make_float2(tf32f(op1.x * tanha(cp1.x)),
                                        tf32f(op1.y * tanha(cp1.y)));
                *(float2*)&hnext[jb * H_STR + bc] = h0;
                *(float2*)&hnext[(jb + 8) * H_STR + bc] = h1;
            }
        }
        __syncthreads();
        float* tmp = hcur; hcur = hnext; hnext = tmp;
    }
    // write final hidden
    for (int i = tid; i < 128 * NB1; i += 512) {
        int j = i & 127, b = i >> 7;
        d_h1[(base + b) * 128 + j] = hcur[j * H_STR + b];
    }
}

// ---------------------------------------------------------------------------
// K2: e2 input projection into K3-permuted layout
// ---------------------------------------------------------------------------
__global__ __launch_bounds__(256, 1) void k2_proj() {
    __shared__ float hsm[32 * 128];
    const int g = threadIdx.x;
    const int t0 = blockIdx.x * 32;
    for (int i = g; i < 32 * 128; i += 256) hsm[i] = d_h1[t0 * 128 + i];
    __syncthreads();
    float acc[32];
#pragma unroll
    for (int r = 0; r < 32; ++r) acc[r] = 0.f;
    for (int k = 0; k < 128; ++k) {
        float w = d_WihT_e2[k * 256 + g];
#pragma unroll
        for (int r = 0; r < 32; ++r) acc[r] = fmaf(hsm[r * 128 + k], w, acc[r]);
    }
    float b = d_bias_e2[g];
    int q = g >> 6, j = g & 63;
    int q2 = q & 1, slot = q >> 1;
    int tid2 = (j >> 4) * 32 + (q2 << 4) + (j & 15);
    int dst = tid2 * 2 + slot;
#pragma unroll
    for (int r = 0; r < 32; ++r) d_pre2[(t0 + r) * 256 + dst] = acc[r] + b;
}

// ---------------------------------------------------------------------------
// K3: e2 serial scan. 1 block, 128 threads, 4096 steps, H=64.
// ---------------------------------------------------------------------------
__global__ __launch_bounds__(128, 1) void k3_e2(const float* __restrict__ Whh_e2) {
    __shared__ float h_sh[2][64];
    const int tid = threadIdx.x;
    const int w = tid >> 5, l = tid & 31;
    const int j = w * 16 + (l & 15);
    const int q2 = l >> 4;
    const int r0 = q2 ? (64 + j) : j;
    const int r1 = q2 ? (192 + j) : (128 + j);

    u64 w0[32], w1[32];
    const u64* W2 = (const u64*)Whh_e2;
#pragma unroll
    for (int k = 0; k < 32; ++k) { w0[k] = W2[r0 * 32 + k]; w1[k] = W2[r1 * 32 + k]; }

    if (tid < 64) h_sh[0][tid] = 0.f;
    float c = 0.f;
    u64 pre_cur = ((const u64*)d_pre2)[tid];
    __syncthreads();

    for (int t = 0; t < 4096; ++t) {
        u64 pre_nxt = (t < 4095) ? ((const u64*)d_pre2)[(t + 1) * 128 + tid] : 0ull;
        const u64* hp = (const u64*)h_sh[t & 1 ? 1 : 0];
        u64 a00 = 0, a01 = 0, a10 = 0, a11 = 0;
#pragma unroll
        for (int k = 0; k < 32; k += 2) {
            u64 h0 = hp[k], h1 = hp[k + 1];
            a00 = ffma2u(w0[k],     h0, a00);
            a01 = ffma2u(w0[k + 1], h1, a01);
            a10 = ffma2u(w1[k],     h0, a10);
            a11 = ffma2u(w1[k + 1], h1, a11);
        }
        a00 = add2(a00, a01);
        a10 = add2(a10, a11);
        float2 v0 = unpk(a00), v1 = unpk(a10);
        float2 pc = unpk(pre_cur);
        float s0 = v0.x + v0.y + pc.x;
        float s1 = v1.x + v1.y + pc.y;
        float act0 = sigm(s0);
        float act1 = q2 ? sigm(s1) : tanha(s1);
        float o0 = __shfl_xor_sync(0xffffffffu, act0, 16);
        float o1 = __shfl_xor_sync(0xffffffffu, act1, 16);
        float iv = q2 ? o0 : act0;
        float fv = q2 ? act0 : o0;
        float gv = q2 ? o1 : act1;
        float ov = q2 ? act1 : o1;
        c = fmaf(fv, c, iv * gv);
        float h = ov * tanha(c);
        if (q2 == 0) h_sh[(t & 1) ^ 1][j] = h;
        __syncthreads();
        pre_cur = pre_nxt;
    }
    if (tid < 64) d_zvec[tid] = h_sh[0][tid];
}

// ---------------------------------------------------------------------------
// K4: decoder (d1 H=128 + fused d2 H=1). 1 block, 512 threads, 140 steps.
// ---------------------------------------------------------------------------
__global__ __launch_bounds__(512, 1) void k4_dec(const float* __restrict__ Wih_d1,
                                                 const float* __restrict__ Wih_d2,
                                                 const float* __restrict__ Whh_d2,
                                                 const float* __restrict__ bih_d2,
                                                 const float* __restrict__ bhh_d2,
                                                 float* __restrict__ out) {
    __shared__ float zsh[64];
    __shared__ float h_sh[128];
    __shared__ float gsh[512];
    const int g = threadIdx.x;
    if (g < 64)  zsh[g] = d_zvec[g];
    if (g < 128) h_sh[g] = 0.f;
    __syncthreads();
    float wz = d_bias_d1[g];
#pragma unroll 8
    for (int k = 0; k < 64; ++k) wz = fmaf(Wih_d1[g * 64 + k], zsh[k], wz);
    const bool is_t = (g >= 256 && g < 384);
    float c = 0.f;

    float wd2[16], b2[4], wh[4];
    float c2 = 0.f, h2 = 0.f;
    if (g < 32) {
#pragma unroll
        for (int q = 0; q < 4; ++q) {
#pragma unroll
            for (int m = 0; m < 4; ++m) wd2[q * 4 + m] = Wih_d2[q * 128 + m * 32 + g];
            b2[q] = bih_d2[q] + bhh_d2[q];
            wh[q] = Whh_d2[q];
        }
    }
    const float4* __restrict__ Wp = d_WT4_d1 + g;
    const u64* hs2 = (const u64*)h_sh;

    for (int t = 0; t < 140; ++t) {
        u64 a0 = 0, a1 = 0;
#pragma unroll 8
        for (int k4 = 0; k4 < 32; ++k4) {
            float4 w = Wp[(size_t)k4 * 512];
            a0 = ffma2u(pack2(w.x, w.y), hs2[2 * k4], a0);
            a1 = ffma2u(pack2(w.z, w.w), hs2[2 * k4 + 1], a1);
        }
        a0 = add2(a0, a1);
        float2 v = unpk(a0);
        float xv = v.x + v.y + wz;
        gsh[g] = is_t ? tanha(xv) : sigm(xv);
        __syncthreads();
        if (g < 128) {
            float iv = gsh[g], fv = gsh[128 + g], gv = gsh[256 + g], ov = gsh[384 + g];
            c = fmaf(fv, c, iv * gv);
            h_sh[g] = ov * tanha(c);
        }
        __syncthreads();
        if (g < 32) {
            float p0 = 0.f, p1 = 0.f, p2 = 0.f, p3 = 0.f;
#pragma unroll
            for (int m = 0; m < 4; ++m) {
                float hv = h_sh[m * 32 + g];
                p0 = fmaf(wd2[0 * 4 + m], hv, p0);
                p1 = fmaf(wd2[1 * 4 + m], hv, p1);
                p2 = fmaf(wd2[2 * 4 + m], hv, p2);
                p3 = fmaf(wd2[3 * 4 + m], hv, p3);
            }
#pragma unroll
            for (int off = 16; off > 0; off >>= 1) {
                p0 += __shfl_xor_sync(0xffffffffu, p0, off);
                p1 += __shfl_xor_sync(0xffffffffu, p1, off);
                p2 += __shfl_xor_sync(0xffffffffu, p2, off);
                p3 += __shfl_xor_sync(0xffffffffu, p3, off);
            }
            float iv2 = sigm(p0 + b2[0] + wh[0] * h2);
            float fv2 = sigm(p1 + b2[1] + wh[1] * h2);
            float gv2 = tanha(p2 + b2[2] + wh[2] * h2);
            float ov2 = sigm(p3 + b2[3] + wh[3] * h2);
            c2 = fmaf(fv2, c2, iv2 * gv2);
            h2 = ov2 * tanha(c2);
            if (g == 0) out[t] = h2;
        }
    }
}

// ---------------------------------------------------------------------------
// Launch
// ---------------------------------------------------------------------------
extern "C" void kernel_launch(void* const* d_in, const int* in_sizes, int n_in,
                              void* d_out, int out_size) {
    const float* x      = (const float*)d_in[0];
    const float* Wih_e1 = (const float*)d_in[1];
    const float* Whh_e1 = (const float*)d_in[2];
    const float* bih_e1 = (const float*)d_in[3];
    const float* bhh_e1 = (const float*)d_in[4];
    const float* Wih_e2 = (const float*)d_in[5];
    const float* Whh_e2 = (const float*)d_in[6];
    const float* bih_e2 = (const float*)d_in[7];
    const float* bhh_e2 = (const float*)d_in[8];
    const float* Wih_d1 = (const float*)d_in[9];
    const float* Whh_d1 = (const float*)d_in[10];
    const float* bih_d1 = (const float*)d_in[11];
    const float* bhh_d1 = (const float*)d_in[12];
    const float* Wih_d2 = (const float*)d_in[13];
    const float* Whh_d2 = (const float*)d_in[14];
    const float* bih_d2 = (const float*)d_in[15];
    const float* bhh_d2 = (const float*)d_in[16];
    float* out = (float*)d_out;
    (void)in_sizes; (void)n_in; (void)out_size;

    cudaFuncSetAttribute(k1_e1, cudaFuncAttributeMaxDynamicSharedMemorySize, K1_SMEM);

    k0_prep<<<64, 256>>>(Whh_e1, bih_e1, bhh_e1, Wih_e2, bih_e2, bhh_e2,
                         Whh_d1, bih_d1, bhh_d1);
    k1_e1<<<64, 512, K1_SMEM>>>(x, Wih_e1);
    k2_proj<<<128, 256>>>();
    k3_e2<<<1, 128>>>(Whh_e2);
    k4_dec<<<1, 512>>>(Wih_d1, Wih_d2, Whh_d2, bih_d2, bhh_d2, out);
}

// round 11
// speedup vs baseline: 1.5163x; 1.1534x over previous
#include <cuda_runtime.h>
#include <cuda_bf16.h>

#define DINL __device__ __forceinline__
typedef unsigned long long u64;
typedef unsigned int u32;

// ---------------------------------------------------------------------------
// helpers
// ---------------------------------------------------------------------------
DINL u64 ffma2u(u64 a, u64 b, u64 c) {
    u64 d;
    asm("fma.rn.f32x2 %0, %1, %2, %3;" : "=l"(d) : "l"(a), "l"(b), "l"(c));
    return d;
}
DINL u64 add2(u64 a, u64 b) {
    u64 d;
    asm("add.rn.f32x2 %0, %1, %2;" : "=l"(d) : "l"(a), "l"(b));
    return d;
}
DINL u64 pack2(float a, float b) {
    u64 u; asm("mov.b64 %0, {%1, %2};" : "=l"(u) : "f"(a), "f"(b)); return u;
}
DINL float2 unpk(u64 u) {
    float2 v; asm("mov.b64 {%0, %1}, %2;" : "=f"(v.x), "=f"(v.y) : "l"(u)); return v;
}
DINL float tanha(float x) {
    float r; asm("tanh.approx.f32 %0, %1;" : "=f"(r) : "f"(x)); return r;
}
DINL float sigm(float x) { return fmaf(tanha(0.5f * x), 0.5f, 0.5f); }
DINL u32 cvt_tf32(float x) {
    u32 r; asm("cvt.rna.tf32.f32 %0, %1;" : "=r"(r) : "f"(x)); return r;
}
DINL float tf32f(float x) { return __uint_as_float(cvt_tf32(x)); }

DINL void mma1688(float& c0, float& c1, float& c2, float& c3,
                  u32 a0, u32 a1, u32 a2, u32 a3, u32 b0, u32 b1) {
    asm("mma.sync.aligned.m16n8k8.row.col.f32.tf32.tf32.f32 "
        "{%0,%1,%2,%3}, {%4,%5,%6,%7}, {%8,%9}, {%0,%1,%2,%3};"
        : "+f"(c0), "+f"(c1), "+f"(c2), "+f"(c3)
        : "r"(a0), "r"(a1), "r"(a2), "r"(a3), "r"(b0), "r"(b1));
}

// ---------------------------------------------------------------------------
// Device-global scratch
// ---------------------------------------------------------------------------
__device__ float4 d_WA_e1[32 * 16 * 32]; // Whh_e1 tf32 mma A-fragments [mt][kt][lane]
__device__ float  d_bias_e1[512];
__device__ float4 d_WT4_d1[32 * 512];    // Whh_d1 transposed
__device__ float  d_bias_d1[512];
__device__ float  d_WihT_e2[128 * 256];  // Wih_e2 transposed [k][g]
__device__ float  d_bias_e2[256];
__device__ float  d_h1[4096 * 128];
__device__ float  d_pre2[4096 * 256];    // K3-permuted layout
__device__ float  d_zvec[64];

// ---------------------------------------------------------------------------
// K0: weight packing / bias folding
// ---------------------------------------------------------------------------
__global__ void k0_prep(const float* __restrict__ Whh_e1,
                        const float* __restrict__ bih_e1, const float* __restrict__ bhh_e1,
                        const float* __restrict__ Wih_e2,
                        const float* __restrict__ bih_e2, const float* __restrict__ bhh_e2,
                        const float* __restrict__ Whh_d1,
                        const float* __restrict__ bih_d1, const float* __restrict__ bhh_d1) {
    int stride = gridDim.x * blockDim.x;
    int tid0 = blockIdx.x * blockDim.x + threadIdx.x;
    for (int idx = tid0; idx < 32 * 16 * 32; idx += stride) {
        int lane = idx & 31, kt = (idx >> 5) & 15, mt = idx >> 9;
        int g = lane >> 2, tg = lane & 3;
        int r0 = mt * 16 + g, r1 = r0 + 8;
        int c0 = kt * 8 + tg, c1 = c0 + 4;
        d_WA_e1[idx] = make_float4(tf32f(Whh_e1[r0 * 128 + c0]),
                                   tf32f(Whh_e1[r1 * 128 + c0]),
                                   tf32f(Whh_e1[r0 * 128 + c1]),
                                   tf32f(Whh_e1[r1 * 128 + c1]));
    }
    for (int i = tid0; i < 32 * 512; i += stride) {
        int k4 = i >> 9, g = i & 511;
        const float* r2 = Whh_d1 + g * 128 + 4 * k4;
        d_WT4_d1[i] = make_float4(r2[0], r2[1], r2[2], r2[3]);
    }
    for (int i = tid0; i < 512; i += stride) {
        d_bias_e1[i] = bih_e1[i] + bhh_e1[i];
        d_bias_d1[i] = bih_d1[i] + bhh_d1[i];
    }
    for (int i = tid0; i < 128 * 256; i += stride) {
        int k = i >> 8, g = i & 255;
        d_WihT_e2[i] = Wih_e2[g * 128 + k];
    }
    for (int i = tid0; i < 256; i += stride) d_bias_e2[i] = bih_e2[i] + bhh_e2[i];
}

// ---------------------------------------------------------------------------
// K1: encoder LSTM 1 on tensor cores (tf32 mma.sync m16n8k8).
// 128 blocks x 512 threads, 32 batch elems per block.
// gates[512,32] = Whh[512,128] @ h[128,32] via HMMA; warp w owns Mtiles {w,w+16}:
//   w<8 -> (i, g~) rows; w>=8 -> (f, o) rows at identical fragment positions.
// ALL warps store activated gates to SMEM; c/h update distributed 512-wide.
// ---------------------------------------------------------------------------
#define NB1 32
#define NT1 4                 // NB1 / 8
#define XS_STR 34
#define H_STR  36
#define G_STR  34
#define SM_X   (140 * XS_STR)
#define SM_H   (128 * H_STR)
#define SM_G   (128 * G_STR)
#define K1_FLOATS (SM_X + 2 * SM_H + 5 * SM_G)
#define K1_SMEM (K1_FLOATS * 4)

__global__ __launch_bounds__(512, 1) void k1_e1(const float* __restrict__ x,
                                                const float* __restrict__ Wih_e1) {
    extern __shared__ float sm[];
    float* xs = sm;                    // [140][34]  xs[t][b]
    float* hA = xs + SM_X;             // [128][36]  h buf0 (tf32 values)
    float* hB = hA + SM_H;
    float* gi = hB + SM_H;             // [128][34] gate i
    float* gf = gi + SM_G;             // gate f
    float* gg = gf + SM_G;             // gate g~
    float* go = gg + SM_G;             // gate o
    float* cs = go + SM_G;             // cell state

    const int tid = threadIdx.x;
    const int w = tid >> 5, lane = tid & 31;
    const int g = lane >> 2, tg = lane & 3;
    const int base = blockIdx.x * NB1;

    for (int i = tid; i < NB1 * 140; i += 512) {
        int b = i / 140, t = i - b * 140;
        xs[t * XS_STR + b] = x[(base + b) * 140 + t];
    }
    for (int i = tid; i < SM_H; i += 512) hA[i] = 0.f;
    for (int i = tid; i < SM_G; i += 512) cs[i] = 0.f;

    const int mt0 = w, mt1 = w + 16;
    const int r00 = mt0 * 16 + g, r01 = r00 + 8;
    const int r10 = mt1 * 16 + g, r11 = r10 + 8;
    const float wi0 = Wih_e1[r00], wi1 = Wih_e1[r01];
    const float wi2 = Wih_e1[r10], wi3 = Wih_e1[r11];
    const float bb0 = d_bias_e1[r00], bb1 = d_bias_e1[r01];
    const float bb2 = d_bias_e1[r10], bb3 = d_bias_e1[r11];
    const int jb = (w & 7) * 16 + g;               // local hidden row
    float* gA = (w < 8) ? gi : gf;                 // C0 target
    float* gB = (w < 8) ? gg : go;                 // C1 target
    const bool loB_tanh = (w < 8);                 // C1 act: tanh for g~, sigm for o
    __syncthreads();

    const float4* __restrict__ WAlo = d_WA_e1 + mt0 * 16 * 32 + lane;
    const float4* __restrict__ WAhi = d_WA_e1 + mt1 * 16 * 32 + lane;

    float* hcur = hA;
    float* hnext = hB;

    for (int t = 0; t < 140; ++t) {
        float C0[NT1][4], C1[NT1][4];
#pragma unroll
        for (int nt = 0; nt < NT1; ++nt) {
            float2 xp = *(const float2*)&xs[t * XS_STR + nt * 8 + 2 * tg];
            C0[nt][0] = fmaf(wi0, xp.x, bb0); C0[nt][1] = fmaf(wi0, xp.y, bb0);
            C0[nt][2] = fmaf(wi1, xp.x, bb1); C0[nt][3] = fmaf(wi1, xp.y, bb1);
            C1[nt][0] = fmaf(wi2, xp.x, bb2); C1[nt][1] = fmaf(wi2, xp.y, bb2);
            C1[nt][2] = fmaf(wi3, xp.x, bb3); C1[nt][3] = fmaf(wi3, xp.y, bb3);
        }
#pragma unroll 4
        for (int kt = 0; kt < 16; ++kt) {
            float4 wlo = WAlo[kt * 32];
            float4 whi = WAhi[kt * 32];
            u32 al0 = __float_as_uint(wlo.x), al1 = __float_as_uint(wlo.y);
            u32 al2 = __float_as_uint(wlo.z), al3 = __float_as_uint(wlo.w);
            u32 ah0 = __float_as_uint(whi.x), ah1 = __float_as_uint(whi.y);
            u32 ah2 = __float_as_uint(whi.z), ah3 = __float_as_uint(whi.w);
            const float* hk = hcur + (kt * 8 + tg) * H_STR;
#pragma unroll
            for (int nt = 0; nt < NT1; ++nt) {
                u32 b0 = __float_as_uint(hk[nt * 8 + g]);
                u32 b1 = __float_as_uint(hk[4 * H_STR + nt * 8 + g]);
                mma1688(C0[nt][0], C0[nt][1], C0[nt][2], C0[nt][3],
                        al0, al1, al2, al3, b0, b1);
                mma1688(C1[nt][0], C1[nt][1], C1[nt][2], C1[nt][3],
                        ah0, ah1, ah2, ah3, b0, b1);
            }
        }
        // activate + store all gates to SMEM
#pragma unroll
        for (int nt = 0; nt < NT1; ++nt) {
            int bc = nt * 8 + 2 * tg;
            float2 a0 = make_float2(sigm(C0[nt][0]), sigm(C0[nt][1]));
            float2 a1 = make_float2(sigm(C0[nt][2]), sigm(C0[nt][3]));
            float2 b0, b1;
            if (loB_tanh) {
                b0 = make_float2(tanha(C1[nt][0]), tanha(C1[nt][1]));
                b1 = make_float2(tanha(C1[nt][2]), tanha(C1[nt][3]));
            } else {
                b0 = make_float2(sigm(C1[nt][0]), sigm(C1[nt][1]));
                b1 = make_float2(sigm(C1[nt][2]), sigm(C1[nt][3]));
            }
            *(float2*)&gA[jb * G_STR + bc]       = a0;
            *(float2*)&gA[(jb + 8) * G_STR + bc] = a1;
            *(float2*)&gB[jb * G_STR + bc]       = b0;
            *(float2*)&gB[(jb + 8) * G_STR + bc] = b1;
        }
        __syncthreads();
        // distributed c/h update: 4096 (j,b) pairs over 512 threads
#pragma unroll
        for (int i = 0; i < 8; ++i) {
            int idx = tid + 512 * i;
            int j = idx & 127, b = idx >> 7;
            float iv = gi[j * G_STR + b];
            float fv = gf[j * G_STR + b];
            float gv = gg[j * G_STR + b];
            float ov = go[j * G_STR + b];
            float cc = fmaf(fv, cs[j * G_STR + b], iv * gv);
            cs[j * G_STR + b] = cc;
            hnext[j * H_STR + b] = tf32f(ov * tanha(cc));
        }
        __syncthreads();
        float* tmp = hcur; hcur = hnext; hnext = tmp;
    }
    for (int i = tid; i < 128 * NB1; i += 512) {
        int j = i & 127, b = i >> 7;
        d_h1[(base + b) * 128 + j] = hcur[j * H_STR + b];
    }
}

// ---------------------------------------------------------------------------
// K2: e2 input projection into K3-permuted layout
// ---------------------------------------------------------------------------
__global__ __launch_bounds__(256, 1) void k2_proj() {
    __shared__ float hsm[32 * 128];
    const int g = threadIdx.x;
    const int t0 = blockIdx.x * 32;
    for (int i = g; i < 32 * 128; i += 256) hsm[i] = d_h1[t0 * 128 + i];
    __syncthreads();
    float acc[32];
#pragma unroll
    for (int r = 0; r < 32; ++r) acc[r] = 0.f;
    for (int k = 0; k < 128; ++k) {
        float w = d_WihT_e2[k * 256 + g];
#pragma unroll
        for (int r = 0; r < 32; ++r) acc[r] = fmaf(hsm[r * 128 + k], w, acc[r]);
    }
    float b = d_bias_e2[g];
    int q = g >> 6, j = g & 63;
    int q2 = q & 1, slot = q >> 1;
    int tid2 = (j >> 4) * 32 + (q2 << 4) + (j & 15);
    int dst = tid2 * 2 + slot;
#pragma unroll
    for (int r = 0; r < 32; ++r) d_pre2[(t0 + r) * 256 + dst] = acc[r] + b;
}

// ---------------------------------------------------------------------------
// K3: e2 serial scan. 1 block, 128 threads, 4096 steps, H=64.
// ---------------------------------------------------------------------------
__global__ __launch_bounds__(128, 1) void k3_e2(const float* __restrict__ Whh_e2) {
    __shared__ float h_sh[2][64];
    const int tid = threadIdx.x;
    const int w = tid >> 5, l = tid & 31;
    const int j = w * 16 + (l & 15);
    const int q2 = l >> 4;
    const int r0 = q2 ? (64 + j) : j;
    const int r1 = q2 ? (192 + j) : (128 + j);

    u64 w0[32], w1[32];
    const u64* W2 = (const u64*)Whh_e2;
#pragma unroll
    for (int k = 0; k < 32; ++k) { w0[k] = W2[r0 * 32 + k]; w1[k] = W2[r1 * 32 + k]; }

    if (tid < 64) h_sh[0][tid] = 0.f;
    float c = 0.f;
    u64 pre_cur = ((const u64*)d_pre2)[tid];
    __syncthreads();

    for (int t = 0; t < 4096; ++t) {
        u64 pre_nxt = (t < 4095) ? ((const u64*)d_pre2)[(t + 1) * 128 + tid] : 0ull;
        const u64* hp = (const u64*)h_sh[t & 1 ? 1 : 0];
        u64 a00 = 0, a01 = 0, a10 = 0, a11 = 0;
#pragma unroll
        for (int k = 0; k < 32; k += 2) {
            u64 h0 = hp[k], h1 = hp[k + 1];
            a00 = ffma2u(w0[k],     h0, a00);
            a01 = ffma2u(w0[k + 1], h1, a01);
            a10 = ffma2u(w1[k],     h0, a10);
            a11 = ffma2u(w1[k + 1], h1, a11);
        }
        a00 = add2(a00, a01);
        a10 = add2(a10, a11);
        float2 v0 = unpk(a00), v1 = unpk(a10);
        float2 pc = unpk(pre_cur);
        float s0 = v0.x + v0.y + pc.x;
        float s1 = v1.x + v1.y + pc.y;
        float act0 = sigm(s0);
        float act1 = q2 ? sigm(s1) : tanha(s1);
        float o0 = __shfl_xor_sync(0xffffffffu, act0, 16);
        float o1 = __shfl_xor_sync(0xffffffffu, act1, 16);
        float iv = q2 ? o0 : act0;
        float fv = q2 ? act0 : o0;
        float gv = q2 ? o1 : act1;
        float ov = q2 ? act1 : o1;
        c = fmaf(fv, c, iv * gv);
        float h = ov * tanha(c);
        if (q2 == 0) h_sh[(t & 1) ^ 1][j] = h;
        __syncthreads();
        pre_cur = pre_nxt;
    }
    if (tid < 64) d_zvec[tid] = h_sh[0][tid];
}

// ---------------------------------------------------------------------------
// K4: decoder (d1 H=128 + fused d2 H=1). 1 block, 512 threads, 140 steps.
// ---------------------------------------------------------------------------
__global__ __launch_bounds__(512, 1) void k4_dec(const float* __restrict__ Wih_d1,
                                                 const float* __restrict__ Wih_d2,
                                                 const float* __restrict__ Whh_d2,
                                                 const float* __restrict__ bih_d2,
                                                 const float* __restrict__ bhh_d2,
                                                 float* __restrict__ out) {
    __shared__ float zsh[64];
    __shared__ float h_sh[128];
    __shared__ float gsh[512];
    const int g = threadIdx.x;
    if (g < 64)  zsh[g] = d_zvec[g];
    if (g < 128) h_sh[g] = 0.f;
    __syncthreads();
    float wz = d_bias_d1[g];
#pragma unroll 8
    for (int k = 0; k < 64; ++k) wz = fmaf(Wih_d1[g * 64 + k], zsh[k], wz);
    const bool is_t = (g >= 256 && g < 384);
    float c = 0.f;

    float wd2[16], b2[4], wh[4];
    float c2 = 0.f, h2 = 0.f;
    if (g < 32) {
#pragma unroll
        for (int q = 0; q < 4; ++q) {
#pragma unroll
            for (int m = 0; m < 4; ++m) wd2[q * 4 + m] = Wih_d2[q * 128 + m * 32 + g];
            b2[q] = bih_d2[q] + bhh_d2[q];
            wh[q] = Whh_d2[q];
        }
    }
    const float4* __restrict__ Wp = d_WT4_d1 + g;
    const u64* hs2 = (const u64*)h_sh;

    for (int t = 0; t < 140; ++t) {
        u64 a0 = 0, a1 = 0;
#pragma unroll 8
        for (int k4 = 0; k4 < 32; ++k4) {
            float4 w = Wp[(size_t)k4 * 512];
            a0 = ffma2u(pack2(w.x, w.y), hs2[2 * k4], a0);
            a1 = ffma2u(pack2(w.z, w.w), hs2[2 * k4 + 1], a1);
        }
        a0 = add2(a0, a1);
        float2 v = unpk(a0);
        float xv = v.x + v.y + wz;
        gsh[g] = is_t ? tanha(xv) : sigm(xv);
        __syncthreads();
        if (g < 128) {
            float iv = gsh[g], fv = gsh[128 + g], gv = gsh[256 + g], ov = gsh[384 + g];
            c = fmaf(fv, c, iv * gv);
            h_sh[g] = ov * tanha(c);
        }
        __syncthreads();
        if (g < 32) {
            float p0 = 0.f, p1 = 0.f, p2 = 0.f, p3 = 0.f;
#pragma unroll
            for (int m = 0; m < 4; ++m) {
                float hv = h_sh[m * 32 + g];
                p0 = fmaf(wd2[0 * 4 + m], hv, p0);
                p1 = fmaf(wd2[1 * 4 + m], hv, p1);
                p2 = fmaf(wd2[2 * 4 + m], hv, p2);
                p3 = fmaf(wd2[3 * 4 + m], hv, p3);
            }
#pragma unroll
            for (int off = 16; off > 0; off >>= 1) {
                p0 += __shfl_xor_sync(0xffffffffu, p0, off);
                p1 += __shfl_xor_sync(0xffffffffu, p1, off);
                p2 += __shfl_xor_sync(0xffffffffu, p2, off);
                p3 += __shfl_xor_sync(0xffffffffu, p3, off);
            }
            float iv2 = sigm(p0 + b2[0] + wh[0] * h2);
            float fv2 = sigm(p1 + b2[1] + wh[1] * h2);
            float gv2 = tanha(p2 + b2[2] + wh[2] * h2);
            float ov2 = sigm(p3 + b2[3] + wh[3] * h2);
            c2 = fmaf(fv2, c2, iv2 * gv2);
            h2 = ov2 * tanha(c2);
            if (g == 0) out[t] = h2;
        }
    }
}

// ---------------------------------------------------------------------------
// Launch
// ---------------------------------------------------------------------------
extern "C" void kernel_launch(void* const* d_in, const int* in_sizes, int n_in,
                              void* d_out, int out_size) {
    const float* x      = (const float*)d_in[0];
    const float* Wih_e1 = (const float*)d_in[1];
    const float* Whh_e1 = (const float*)d_in[2];
    const float* bih_e1 = (const float*)d_in[3];
    const float* bhh_e1 = (const float*)d_in[4];
    const float* Wih_e2 = (const float*)d_in[5];
    const float* Whh_e2 = (const float*)d_in[6];
    const float* bih_e2 = (const float*)d_in[7];
    const float* bhh_e2 = (const float*)d_in[8];
    const float* Wih_d1 = (const float*)d_in[9];
    const float* Whh_d1 = (const float*)d_in[10];
    const float* bih_d1 = (const float*)d_in[11];
    const float* bhh_d1 = (const float*)d_in[12];
    const float* Wih_d2 = (const float*)d_in[13];
    const float* Whh_d2 = (const float*)d_in[14];
    const float* bih_d2 = (const float*)d_in[15];
    const float* bhh_d2 = (const float*)d_in[16];
    float* out = (float*)d_out;
    (void)in_sizes; (void)n_in; (void)out_size;

    cudaFuncSetAttribute(k1_e1, cudaFuncAttributeMaxDynamicSharedMemorySize, K1_SMEM);

    k0_prep<<<64, 256>>>(Whh_e1, bih_e1, bhh_e1, Wih_e2, bih_e2, bhh_e2,
                         Whh_d1, bih_d1, bhh_d1);
    k1_e1<<<128, 512, K1_SMEM>>>(x, Wih_e1);
    k2_proj<<<128, 256>>>();
    k3_e2<<<1, 128>>>(Whh_e2);
    k4_dec<<<1, 512>>>(Wih_d1, Wih_d2, Whh_d2, bih_d2, bhh_d2, out);
}

// round 12
// speedup vs baseline: 2.2411x; 1.4780x over previous
#include <cuda_runtime.h>
#include <cuda_bf16.h>

#define DINL __device__ __forceinline__
typedef unsigned long long u64;
typedef unsigned int u32;

// ---------------------------------------------------------------------------
// helpers
// ---------------------------------------------------------------------------
DINL u64 ffma2u(u64 a, u64 b, u64 c) {
    u64 d;
    asm("fma.rn.f32x2 %0, %1, %2, %3;" : "=l"(d) : "l"(a), "l"(b), "l"(c));
    return d;
}
DINL u64 add2(u64 a, u64 b) {
    u64 d;
    asm("add.rn.f32x2 %0, %1, %2;" : "=l"(d) : "l"(a), "l"(b));
    return d;
}
DINL u64 pack2(float a, float b) {
    u64 u; asm("mov.b64 %0, {%1, %2};" : "=l"(u) : "f"(a), "f"(b)); return u;
}
DINL float2 unpk(u64 u) {
    float2 v; asm("mov.b64 {%0, %1}, %2;" : "=f"(v.x), "=f"(v.y) : "l"(u)); return v;
}
DINL float tanha(float x) {
    float r; asm("tanh.approx.f32 %0, %1;" : "=f"(r) : "f"(x)); return r;
}
DINL float sigm(float x) { return fmaf(tanha(0.5f * x), 0.5f, 0.5f); }

// bf16x2 pack: lo = first arg, hi = second arg
DINL u32 bfpack(float lo, float hi) {
    __nv_bfloat162 t = __floats2bfloat162_rn(lo, hi);
    return *reinterpret_cast<u32*>(&t);
}

DINL void mma16816(float& c0, float& c1, float& c2, float& c3,
                   u32 a0, u32 a1, u32 a2, u32 a3, u32 b0, u32 b1) {
    asm("mma.sync.aligned.m16n8k16.row.col.f32.bf16.bf16.f32 "
        "{%0,%1,%2,%3}, {%4,%5,%6,%7}, {%8,%9}, {%0,%1,%2,%3};"
        : "+f"(c0), "+f"(c1), "+f"(c2), "+f"(c3)
        : "r"(a0), "r"(a1), "r"(a2), "r"(a3), "r"(b0), "r"(b1));
}

// ---------------------------------------------------------------------------
// Device-global scratch
// ---------------------------------------------------------------------------
__device__ uint4  d_WAb_e1[32 * 8 * 32]; // Whh_e1 bf16 mma A-fragments [mt][kt][lane]
__device__ float  d_bias_e1[512];
__device__ float4 d_WT4_d1[32 * 512];    // Whh_d1 transposed
__device__ float  d_bias_d1[512];
__device__ float  d_WihT_e2[128 * 256];  // Wih_e2 transposed [k][g]
__device__ float  d_bias_e2[256];
__device__ float  d_h1[4096 * 128];
__device__ float  d_pre2[4096 * 256];    // K3-permuted layout
__device__ float  d_zvec[64];

// ---------------------------------------------------------------------------
// K0: weight packing / bias folding
// ---------------------------------------------------------------------------
__global__ void k0_prep(const float* __restrict__ Whh_e1,
                        const float* __restrict__ bih_e1, const float* __restrict__ bhh_e1,
                        const float* __restrict__ Wih_e2,
                        const float* __restrict__ bih_e2, const float* __restrict__ bhh_e2,
                        const float* __restrict__ Whh_d1,
                        const float* __restrict__ bih_d1, const float* __restrict__ bhh_d1) {
    int stride = gridDim.x * blockDim.x;
    int tid0 = blockIdx.x * blockDim.x + threadIdx.x;
    // Whh_e1 -> bf16 m16n8k16 A fragments
    for (int idx = tid0; idx < 32 * 8 * 32; idx += stride) {
        int lane = idx & 31, kt = (idx >> 5) & 7, mt = idx >> 8;
        int g = lane >> 2, tg = lane & 3;
        int r0 = mt * 16 + g, r1 = r0 + 8;
        int kb = kt * 16;
        uint4 v;
        v.x = bfpack(Whh_e1[r0 * 128 + kb + 2 * tg],     Whh_e1[r0 * 128 + kb + 2 * tg + 1]);
        v.y = bfpack(Whh_e1[r1 * 128 + kb + 2 * tg],     Whh_e1[r1 * 128 + kb + 2 * tg + 1]);
        v.z = bfpack(Whh_e1[r0 * 128 + kb + 2 * tg + 8], Whh_e1[r0 * 128 + kb + 2 * tg + 9]);
        v.w = bfpack(Whh_e1[r1 * 128 + kb + 2 * tg + 8], Whh_e1[r1 * 128 + kb + 2 * tg + 9]);
        d_WAb_e1[idx] = v;
    }
    for (int i = tid0; i < 32 * 512; i += stride) {
        int k4 = i >> 9, g = i & 511;
        const float* r2 = Whh_d1 + g * 128 + 4 * k4;
        d_WT4_d1[i] = make_float4(r2[0], r2[1], r2[2], r2[3]);
    }
    for (int i = tid0; i < 512; i += stride) {
        d_bias_e1[i] = bih_e1[i] + bhh_e1[i];
        d_bias_d1[i] = bih_d1[i] + bhh_d1[i];
    }
    for (int i = tid0; i < 128 * 256; i += stride) {
        int k = i >> 8, g = i & 255;
        d_WihT_e2[i] = Wih_e2[g * 128 + k];
    }
    for (int i = tid0; i < 256; i += stride) d_bias_e2[i] = bih_e2[i] + bhh_e2[i];
}

// ---------------------------------------------------------------------------
// K1: encoder LSTM 1 on tensor cores (bf16 mma.sync m16n8k16).
// 128 blocks x 512 threads, 32 batch elems per block.
// gates[512,32] = Whh[512,128] @ h[128,32]; warp w owns Mtiles {w, w+16}.
// h in SMEM as k-pair-packed bf16x2 [64][40] u32; gates f32 [128][36];
// c in registers of phase-B owner threads (b-major mapping, conflict-free).
// ---------------------------------------------------------------------------
#define NB1 32
#define NT1 4
#define XS_STR 34
#define G_STR  36
#define H2_STR 40                 // u32 stride for packed h rows
#define SM_X   (140 * XS_STR)
#define SM_G   (128 * G_STR)
#define SM_H2  (64 * H2_STR)      // u32 count per h buffer
#define K1_SMEM ((SM_X + 4 * SM_G + 2 * SM_H2) * 4)

__global__ __launch_bounds__(512, 1) void k1_e1(const float* __restrict__ x,
                                                const float* __restrict__ Wih_e1) {
    extern __shared__ float sm[];
    float* xs = sm;                      // [140][34]
    float* gi = xs + SM_X;               // [128][36]
    float* gf = gi + SM_G;
    float* gg = gf + SM_G;
    float* go = gg + SM_G;
    u32*   h2A = (u32*)(go + SM_G);      // [64][40] packed bf16x2 (k-pairs)
    u32*   h2B = h2A + SM_H2;

    const int tid = threadIdx.x;
    const int w = tid >> 5, lane = tid & 31;
    const int g = lane >> 2, tg = lane & 3;
    const int base = blockIdx.x * NB1;

    for (int i = tid; i < NB1 * 140; i += 512) {
        int b = i / 140, t = i - b * 140;
        xs[t * XS_STR + b] = x[(base + b) * 140 + t];
    }
    for (int i = tid; i < 2 * SM_H2; i += 512) h2A[i] = 0u;

    const int mt0 = w, mt1 = w + 16;
    const int r00 = mt0 * 16 + g, r01 = r00 + 8;
    const int r10 = mt1 * 16 + g, r11 = r10 + 8;
    const float wi0 = Wih_e1[r00], wi1 = Wih_e1[r01];
    const float wi2 = Wih_e1[r10], wi3 = Wih_e1[r11];
    const float bb0 = d_bias_e1[r00], bb1 = d_bias_e1[r01];
    const float bb2 = d_bias_e1[r10], bb3 = d_bias_e1[r11];
    const int jb = (w & 7) * 16 + g;               // local hidden row for gate store
    float* gA = (w < 8) ? gi : gf;
    float* gB = (w < 8) ? gg : go;
    const bool loB_tanh = (w < 8);

    // phase-B ownership (fixed across t): iter i -> kp = (tid>>5) + 16*i, b = tid&31
    float cr[8];
#pragma unroll
    for (int i = 0; i < 8; ++i) cr[i] = 0.f;
    const int pb_b  = tid & 31;
    const int pb_kp0 = tid >> 5;
    __syncthreads();

    const uint4* __restrict__ WAlo = d_WAb_e1 + mt0 * 8 * 32 + lane;
    const uint4* __restrict__ WAhi = d_WAb_e1 + mt1 * 8 * 32 + lane;

    u32* hcur = h2A;
    u32* hnext = h2B;

    for (int t = 0; t < 140; ++t) {
        float C0[NT1][4], C1[NT1][4];
#pragma unroll
        for (int nt = 0; nt < NT1; ++nt) {
            float2 xp = *(const float2*)&xs[t * XS_STR + nt * 8 + 2 * tg];
            C0[nt][0] = fmaf(wi0, xp.x, bb0); C0[nt][1] = fmaf(wi0, xp.y, bb0);
            C0[nt][2] = fmaf(wi1, xp.x, bb1); C0[nt][3] = fmaf(wi1, xp.y, bb1);
            C1[nt][0] = fmaf(wi2, xp.x, bb2); C1[nt][1] = fmaf(wi2, xp.y, bb2);
            C1[nt][2] = fmaf(wi3, xp.x, bb3); C1[nt][3] = fmaf(wi3, xp.y, bb3);
        }
#pragma unroll
        for (int kt = 0; kt < 8; ++kt) {
            uint4 wlo = WAlo[kt * 32];
            uint4 whi = WAhi[kt * 32];
            const u32* hk0 = hcur + (kt * 8 + tg) * H2_STR;       // b0 k-pair row
            const u32* hk1 = hcur + (kt * 8 + tg + 4) * H2_STR;   // b1 k-pair row
#pragma unroll
            for (int nt = 0; nt < NT1; ++nt) {
                u32 b0 = hk0[nt * 8 + g];
                u32 b1 = hk1[nt * 8 + g];
                mma16816(C0[nt][0], C0[nt][1], C0[nt][2], C0[nt][3],
                         wlo.x, wlo.y, wlo.z, wlo.w, b0, b1);
                mma16816(C1[nt][0], C1[nt][1], C1[nt][2], C1[nt][3],
                         whi.x, whi.y, whi.z, whi.w, b0, b1);
            }
        }
        // activate + store gates (f32, float2 at even stride 36)
#pragma unroll
        for (int nt = 0; nt < NT1; ++nt) {
            int bc = nt * 8 + 2 * tg;
            float2 a0 = make_float2(sigm(C0[nt][0]), sigm(C0[nt][1]));
            float2 a1 = make_float2(sigm(C0[nt][2]), sigm(C0[nt][3]));
            float2 b0, b1;
            if (loB_tanh) {
                b0 = make_float2(tanha(C1[nt][0]), tanha(C1[nt][1]));
                b1 = make_float2(tanha(C1[nt][2]), tanha(C1[nt][3]));
            } else {
                b0 = make_float2(sigm(C1[nt][0]), sigm(C1[nt][1]));
                b1 = make_float2(sigm(C1[nt][2]), sigm(C1[nt][3]));
            }
            *(float2*)&gA[jb * G_STR + bc]       = a0;
            *(float2*)&gA[(jb + 8) * G_STR + bc] = a1;
            *(float2*)&gB[jb * G_STR + bc]       = b0;
            *(float2*)&gB[(jb + 8) * G_STR + bc] = b1;
        }
        __syncthreads();
        // phase B: b-major (lane = batch) -> conflict-free LDS/STS; c in regs
#pragma unroll
        for (int i = 0; i < 4; ++i) {
            int kp = pb_kp0 + 16 * i;
            int j0 = 2 * kp, j1 = j0 + 1;
            float i0 = gi[j0 * G_STR + pb_b], i1 = gi[j1 * G_STR + pb_b];
            float f0 = gf[j0 * G_STR + pb_b], f1 = gf[j1 * G_STR + pb_b];
            float g0 = gg[j0 * G_STR + pb_b], g1 = gg[j1 * G_STR + pb_b];
            float o0 = go[j0 * G_STR + pb_b], o1 = go[j1 * G_STR + pb_b];
            cr[2 * i]     = fmaf(f0, cr[2 * i],     i0 * g0);
            cr[2 * i + 1] = fmaf(f1, cr[2 * i + 1], i1 * g1);
            float h0 = o0 * tanha(cr[2 * i]);
            float h1 = o1 * tanha(cr[2 * i + 1]);
            hnext[kp * H2_STR + pb_b] = bfpack(h0, h1);
            if (t == 139) {
                d_h1[(base + pb_b) * 128 + j0] = h0;
                d_h1[(base + pb_b) * 128 + j1] = h1;
            }
        }
        __syncthreads();
        u32* tmp = hcur; hcur = hnext; hnext = tmp;
    }
}

// ---------------------------------------------------------------------------
// K2: e2 input projection into K3-permuted layout
// ---------------------------------------------------------------------------
__global__ __launch_bounds__(256, 1) void k2_proj() {
    __shared__ float hsm[32 * 128];
    const int g = threadIdx.x;
    const int t0 = blockIdx.x * 32;
    for (int i = g; i < 32 * 128; i += 256) hsm[i] = d_h1[t0 * 128 + i];
    __syncthreads();
    float acc[32];
#pragma unroll
    for (int r = 0; r < 32; ++r) acc[r] = 0.f;
    for (int k = 0; k < 128; ++k) {
        float w = d_WihT_e2[k * 256 + g];
#pragma unroll
        for (int r = 0; r < 32; ++r) acc[r] = fmaf(hsm[r * 128 + k], w, acc[r]);
    }
    float b = d_bias_e2[g];
    int q = g >> 6, j = g & 63;
    int q2 = q & 1, slot = q >> 1;
    int tid2 = (j >> 4) * 32 + (q2 << 4) + (j & 15);
    int dst = tid2 * 2 + slot;
#pragma unroll
    for (int r = 0; r < 32; ++r) d_pre2[(t0 + r) * 256 + dst] = acc[r] + b;
}

// ---------------------------------------------------------------------------
// K3: e2 serial scan. 1 block, 128 threads, 4096 steps, H=64.
// 8 accumulators (8-deep chains), pre seeded into accumulators.
// ---------------------------------------------------------------------------
__global__ __launch_bounds__(128, 1) void k3_e2(const float* __restrict__ Whh_e2) {
    __shared__ float h_sh[2][64];
    const int tid = threadIdx.x;
    const int w = tid >> 5, l = tid & 31;
    const int j = w * 16 + (l & 15);
    const int q2 = l >> 4;
    const int r0 = q2 ? (64 + j) : j;
    const int r1 = q2 ? (192 + j) : (128 + j);

    u64 w0[32], w1[32];
    const u64* W2 = (const u64*)Whh_e2;
#pragma unroll
    for (int k = 0; k < 32; ++k) { w0[k] = W2[r0 * 32 + k]; w1[k] = W2[r1 * 32 + k]; }

    if (tid < 64) h_sh[0][tid] = 0.f;
    float c = 0.f;
    u64 pre_cur = ((const u64*)d_pre2)[tid];
    __syncthreads();

    for (int t = 0; t < 4096; ++t) {
        u64 pre_nxt = (t < 4095) ? ((const u64*)d_pre2)[(t + 1) * 128 + tid] : 0ull;
        const u64* hp = (const u64*)h_sh[t & 1 ? 1 : 0];
        float2 pc = unpk(pre_cur);
        u64 a00 = pack2(pc.x, 0.f), a01 = 0, a02 = 0, a03 = 0;
        u64 a10 = pack2(pc.y, 0.f), a11 = 0, a12 = 0, a13 = 0;
#pragma unroll
        for (int k = 0; k < 32; k += 4) {
            u64 h0 = hp[k], h1 = hp[k + 1], h2 = hp[k + 2], h3 = hp[k + 3];
            a00 = ffma2u(w0[k],     h0, a00);
            a01 = ffma2u(w0[k + 1], h1, a01);
            a02 = ffma2u(w0[k + 2], h2, a02);
            a03 = ffma2u(w0[k + 3], h3, a03);
            a10 = ffma2u(w1[k],     h0, a10);
            a11 = ffma2u(w1[k + 1], h1, a11);
            a12 = ffma2u(w1[k + 2], h2, a12);
            a13 = ffma2u(w1[k + 3], h3, a13);
        }
        a00 = add2(add2(a00, a01), add2(a02, a03));
        a10 = add2(add2(a10, a11), add2(a12, a13));
        float2 v0 = unpk(a00), v1 = unpk(a10);
        float s0 = v0.x + v0.y;
        float s1 = v1.x + v1.y;
        float act0 = sigm(s0);
        float act1 = q2 ? sigm(s1) : tanha(s1);
        float o0 = __shfl_xor_sync(0xffffffffu, act0, 16);
        float o1 = __shfl_xor_sync(0xffffffffu, act1, 16);
        float iv = q2 ? o0 : act0;
        float fv = q2 ? act0 : o0;
        float gv = q2 ? o1 : act1;
        float ov = q2 ? act1 : o1;
        c = fmaf(fv, c, iv * gv);
        float h = ov * tanha(c);
        if (q2 == 0) h_sh[(t & 1) ^ 1][j] = h;
        __syncthreads();
        pre_cur = pre_nxt;
    }
    if (tid < 64) d_zvec[tid] = h_sh[0][tid];
}

// ---------------------------------------------------------------------------
// K4: decoder (d1 H=128 + fused d2 H=1). 1 block, 512 threads, 140 steps.
// ---------------------------------------------------------------------------
__global__ __launch_bounds__(512, 1) void k4_dec(const float* __restrict__ Wih_d1,
                                                 const float* __restrict__ Wih_d2,
                                                 const float* __restrict__ Whh_d2,
                                                 const float* __restrict__ bih_d2,
                                                 const float* __restrict__ bhh_d2,
                                                 float* __restrict__ out) {
    __shared__ float zsh[64];
    __shared__ float h_sh[128];
    __shared__ float gsh[512];
    const int g = threadIdx.x;
    if (g < 64)  zsh[g] = d_zvec[g];
    if (g < 128) h_sh[g] = 0.f;
    __syncthreads();
    float wz = d_bias_d1[g];
#pragma unroll 8
    for (int k = 0; k < 64; ++k) wz = fmaf(Wih_d1[g * 64 + k], zsh[k], wz);
    const bool is_t = (g >= 256 && g < 384);
    float c = 0.f;

    float wd2[16], b2[4], wh[4];
    float c2 = 0.f, h2 = 0.f;
    if (g < 32) {
#pragma unroll
        for (int q = 0; q < 4; ++q) {
#pragma unroll
            for (int m = 0; m < 4; ++m) wd2[q * 4 + m] = Wih_d2[q * 128 + m * 32 + g];
            b2[q] = bih_d2[q] + bhh_d2[q];
            wh[q] = Whh_d2[q];
        }
    }
    const float4* __restrict__ Wp = d_WT4_d1 + g;
    const u64* hs2 = (const u64*)h_sh;

    for (int t = 0; t < 140; ++t) {
        u64 a0 = 0, a1 = 0;
#pragma unroll 8
        for (int k4 = 0; k4 < 32; ++k4) {
            float4 w = Wp[(size_t)k4 * 512];
            a0 = ffma2u(pack2(w.x, w.y), hs2[2 * k4], a0);
            a1 = ffma2u(pack2(w.z, w.w), hs2[2 * k4 + 1], a1);
        }
        a0 = add2(a0, a1);
        float2 v = unpk(a0);
        float xv = v.x + v.y + wz;
        gsh[g] = is_t ? tanha(xv) : sigm(xv);
        __syncthreads();
        if (g < 128) {
            float iv = gsh[g], fv = gsh[128 + g], gv = gsh[256 + g], ov = gsh[384 + g];
            c = fmaf(fv, c, iv * gv);
            h_sh[g] = ov * tanha(c);
        }
        __syncthreads();
        if (g < 32) {
            float p0 = 0.f, p1 = 0.f, p2 = 0.f, p3 = 0.f;
#pragma unroll
            for (int m = 0; m < 4; ++m) {
                float hv = h_sh[m * 32 + g];
                p0 = fmaf(wd2[0 * 4 + m], hv, p0);
                p1 = fmaf(wd2[1 * 4 + m], hv, p1);
                p2 = fmaf(wd2[2 * 4 + m], hv, p2);
                p3 = fmaf(wd2[3 * 4 + m], hv, p3);
            }
#pragma unroll
            for (int off = 16; off > 0; off >>= 1) {
                p0 += __shfl_xor_sync(0xffffffffu, p0, off);
                p1 += __shfl_xor_sync(0xffffffffu, p1, off);
                p2 += __shfl_xor_sync(0xffffffffu, p2, off);
                p3 += __shfl_xor_sync(0xffffffffu, p3, off);
            }
            float iv2 = sigm(p0 + b2[0] + wh[0] * h2);
            float fv2 = sigm(p1 + b2[1] + wh[1] * h2);
            float gv2 = tanha(p2 + b2[2] + wh[2] * h2);
            float ov2 = sigm(p3 + b2[3] + wh[3] * h2);
            c2 = fmaf(fv2, c2, iv2 * gv2);
            h2 = ov2 * tanha(c2);
            if (g == 0) out[t] = h2;
        }
    }
}

// ---------------------------------------------------------------------------
// Launch
// ---------------------------------------------------------------------------
extern "C" void kernel_launch(void* const* d_in, const int* in_sizes, int n_in,
                              void* d_out, int out_size) {
    const float* x      = (const float*)d_in[0];
    const float* Wih_e1 = (const float*)d_in[1];
    const float* Whh_e1 = (const float*)d_in[2];
    const float* bih_e1 = (const float*)d_in[3];
    const float* bhh_e1 = (const float*)d_in[4];
    const float* Wih_e2 = (const float*)d_in[5];
    const float* Whh_e2 = (const float*)d_in[6];
    const float* bih_e2 = (const float*)d_in[7];
    const float* bhh_e2 = (const float*)d_in[8];
    const float* Wih_d1 = (const float*)d_in[9];
    const float* Whh_d1 = (const float*)d_in[10];
    const float* bih_d1 = (const float*)d_in[11];
    const float* bhh_d1 = (const float*)d_in[12];
    const float* Wih_d2 = (const float*)d_in[13];
    const float* Whh_d2 = (const float*)d_in[14];
    const float* bih_d2 = (const float*)d_in[15];
    const float* bhh_d2 = (const float*)d_in[16];
    float* out = (float*)d_out;
    (void)in_sizes; (void)n_in; (void)out_size;

    cudaFuncSetAttribute(k1_e1, cudaFuncAttributeMaxDynamicSharedMemorySize, K1_SMEM);

    k0_prep<<<64, 256>>>(Whh_e1, bih_e1, bhh_e1, Wih_e2, bih_e2, bhh_e2,
                         Whh_d1, bih_d1, bhh_d1);
    k1_e1<<<128, 512, K1_SMEM>>>(x, Wih_e1);
    k2_proj<<<128, 256>>>();
    k3_e2<<<1, 128>>>(Whh_e2);
    k4_dec<<<1, 512>>>(Wih_d1, Wih_d2, Whh_d2, bih_d2, bhh_d2, out);
}

// round 14
// speedup vs baseline: 2.5270x; 1.1276x over previous
#include <cuda_runtime.h>
#include <cuda_bf16.h>

#define DINL __device__ __forceinline__
typedef unsigned long long u64;
typedef unsigned int u32;

// ---------------------------------------------------------------------------
// helpers
// ---------------------------------------------------------------------------
DINL u64 ffma2u(u64 a, u64 b, u64 c) {
    u64 d;
    asm("fma.rn.f32x2 %0, %1, %2, %3;" : "=l"(d) : "l"(a), "l"(b), "l"(c));
    return d;
}
DINL u64 add2(u64 a, u64 b) {
    u64 d;
    asm("add.rn.f32x2 %0, %1, %2;" : "=l"(d) : "l"(a), "l"(b));
    return d;
}
DINL u64 pack2(float a, float b) {
    u64 u; asm("mov.b64 %0, {%1, %2};" : "=l"(u) : "f"(a), "f"(b)); return u;
}
DINL float2 unpk(u64 u) {
    float2 v; asm("mov.b64 {%0, %1}, %2;" : "=f"(v.x), "=f"(v.y) : "l"(u)); return v;
}
DINL float tanha(float x) {
    float r; asm("tanh.approx.f32 %0, %1;" : "=f"(r) : "f"(x)); return r;
}
DINL float sigm(float x) { return fmaf(tanha(0.5f * x), 0.5f, 0.5f); }

DINL u32 bfpack(float lo, float hi) {
    __nv_bfloat162 t = __floats2bfloat162_rn(lo, hi);
    return *reinterpret_cast<u32*>(&t);
}

DINL void mma16816(float& c0, float& c1, float& c2, float& c3,
                   u32 a0, u32 a1, u32 a2, u32 a3, u32 b0, u32 b1) {
    asm("mma.sync.aligned.m16n8k16.row.col.f32.bf16.bf16.f32 "
        "{%0,%1,%2,%3}, {%4,%5,%6,%7}, {%8,%9}, {%0,%1,%2,%3};"
        : "+f"(c0), "+f"(c1), "+f"(c2), "+f"(c3)
        : "r"(a0), "r"(a1), "r"(a2), "r"(a3), "r"(b0), "r"(b1));
}

// ---------------------------------------------------------------------------
// Device-global scratch
// ---------------------------------------------------------------------------
__device__ uint4  d_WAb_e1[32 * 8 * 32]; // Whh_e1 bf16 A-fragments [mt][kt][lane]
__device__ float  d_bias_e1[512];
__device__ float4 d_WT4_d1[32 * 512];    // Whh_d1 transposed (fp32, streamed in K4)
__device__ float  d_bias_d1[512];
__device__ float  d_WihT_e2[128 * 256];  // Wih_e2 transposed [k][g]
__device__ float  d_bias_e2[256];
__device__ float  d_h1[4096 * 128];
__device__ float  d_pre2[4096 * 256];    // K3-permuted layout
__device__ float  d_zvec[64];

// ---------------------------------------------------------------------------
// K0: weight packing / bias folding
// ---------------------------------------------------------------------------
__global__ void k0_prep(const float* __restrict__ Whh_e1,
                        const float* __restrict__ bih_e1, const float* __restrict__ bhh_e1,
                        const float* __restrict__ Wih_e2,
                        const float* __restrict__ bih_e2, const float* __restrict__ bhh_e2,
                        const float* __restrict__ Whh_d1,
                        const float* __restrict__ bih_d1, const float* __restrict__ bhh_d1) {
    int stride = gridDim.x * blockDim.x;
    int tid0 = blockIdx.x * blockDim.x + threadIdx.x;
    // Whh_e1 -> bf16 m16n8k16 A fragments
    for (int idx = tid0; idx < 32 * 8 * 32; idx += stride) {
        int lane = idx & 31, kt = (idx >> 5) & 7, mt = idx >> 8;
        int g = lane >> 2, tg = lane & 3;
        int r0 = mt * 16 + g, r1 = r0 + 8;
        int kb = kt * 16;
        uint4 v;
        v.x = bfpack(Whh_e1[r0 * 128 + kb + 2 * tg],     Whh_e1[r0 * 128 + kb + 2 * tg + 1]);
        v.y = bfpack(Whh_e1[r1 * 128 + kb + 2 * tg],     Whh_e1[r1 * 128 + kb + 2 * tg + 1]);
        v.z = bfpack(Whh_e1[r0 * 128 + kb + 2 * tg + 8], Whh_e1[r0 * 128 + kb + 2 * tg + 9]);
        v.w = bfpack(Whh_e1[r1 * 128 + kb + 2 * tg + 8], Whh_e1[r1 * 128 + kb + 2 * tg + 9]);
        d_WAb_e1[idx] = v;
    }
    // Whh_d1 transposed fp32 (K4 streams it)
    for (int i = tid0; i < 32 * 512; i += stride) {
        int k4 = i >> 9, g = i & 511;
        const float* r2 = Whh_d1 + g * 128 + 4 * k4;
        d_WT4_d1[i] = make_float4(r2[0], r2[1], r2[2], r2[3]);
    }
    for (int i = tid0; i < 512; i += stride) {
        d_bias_e1[i] = bih_e1[i] + bhh_e1[i];
        d_bias_d1[i] = bih_d1[i] + bhh_d1[i];
    }
    for (int i = tid0; i < 128 * 256; i += stride) {
        int k = i >> 8, g = i & 255;
        d_WihT_e2[i] = Wih_e2[g * 128 + k];
    }
    for (int i = tid0; i < 256; i += stride) d_bias_e2[i] = bih_e2[i] + bhh_e2[i];
}

// ---------------------------------------------------------------------------
// K1: encoder LSTM 1 on tensor cores (bf16 mma.sync m16n8k16). R12-identical.
// ---------------------------------------------------------------------------
#define NB1 32
#define NT1 4
#define XS_STR 34
#define G_STR  36
#define H2_STR 40
#define SM_X   (140 * XS_STR)
#define SM_G   (128 * G_STR)
#define SM_H2  (64 * H2_STR)
#define K1_SMEM ((SM_X + 4 * SM_G + 2 * SM_H2) * 4)

__global__ __launch_bounds__(512, 1) void k1_e1(const float* __restrict__ x,
                                                const float* __restrict__ Wih_e1) {
    extern __shared__ float sm[];
    float* xs = sm;
    float* gi = xs + SM_X;
    float* gf = gi + SM_G;
    float* gg = gf + SM_G;
    float* go = gg + SM_G;
    u32*   h2A = (u32*)(go + SM_G);
    u32*   h2B = h2A + SM_H2;

    const int tid = threadIdx.x;
    const int w = tid >> 5, lane = tid & 31;
    const int g = lane >> 2, tg = lane & 3;
    const int base = blockIdx.x * NB1;

    for (int i = tid; i < NB1 * 140; i += 512) {
        int b = i / 140, t = i - b * 140;
        xs[t * XS_STR + b] = x[(base + b) * 140 + t];
    }
    for (int i = tid; i < 2 * SM_H2; i += 512) h2A[i] = 0u;

    const int mt0 = w, mt1 = w + 16;
    const int r00 = mt0 * 16 + g, r01 = r00 + 8;
    const int r10 = mt1 * 16 + g, r11 = r10 + 8;
    const float wi0 = Wih_e1[r00], wi1 = Wih_e1[r01];
    const float wi2 = Wih_e1[r10], wi3 = Wih_e1[r11];
    const float bb0 = d_bias_e1[r00], bb1 = d_bias_e1[r01];
    const float bb2 = d_bias_e1[r10], bb3 = d_bias_e1[r11];
    const int jb = (w & 7) * 16 + g;
    float* gA = (w < 8) ? gi : gf;
    float* gB = (w < 8) ? gg : go;
    const bool loB_tanh = (w < 8);

    float cr[8];
#pragma unroll
    for (int i = 0; i < 8; ++i) cr[i] = 0.f;
    const int pb_b  = tid & 31;
    const int pb_kp0 = tid >> 5;
    __syncthreads();

    const uint4* __restrict__ WAlo = d_WAb_e1 + mt0 * 8 * 32 + lane;
    const uint4* __restrict__ WAhi = d_WAb_e1 + mt1 * 8 * 32 + lane;

    u32* hcur = h2A;
    u32* hnext = h2B;

    for (int t = 0; t < 140; ++t) {
        float C0[NT1][4], C1[NT1][4];
#pragma unroll
        for (int nt = 0; nt < NT1; ++nt) {
            float2 xp = *(const float2*)&xs[t * XS_STR + nt * 8 + 2 * tg];
            C0[nt][0] = fmaf(wi0, xp.x, bb0); C0[nt][1] = fmaf(wi0, xp.y, bb0);
            C0[nt][2] = fmaf(wi1, xp.x, bb1); C0[nt][3] = fmaf(wi1, xp.y, bb1);
            C1[nt][0] = fmaf(wi2, xp.x, bb2); C1[nt][1] = fmaf(wi2, xp.y, bb2);
            C1[nt][2] = fmaf(wi3, xp.x, bb3); C1[nt][3] = fmaf(wi3, xp.y, bb3);
        }
#pragma unroll
        for (int kt = 0; kt < 8; ++kt) {
            uint4 wlo = WAlo[kt * 32];
            uint4 whi = WAhi[kt * 32];
            const u32* hk0 = hcur + (kt * 8 + tg) * H2_STR;
            const u32* hk1 = hcur + (kt * 8 + tg + 4) * H2_STR;
#pragma unroll
            for (int nt = 0; nt < NT1; ++nt) {
                u32 b0 = hk0[nt * 8 + g];
                u32 b1 = hk1[nt * 8 + g];
                mma16816(C0[nt][0], C0[nt][1], C0[nt][2], C0[nt][3],
                         wlo.x, wlo.y, wlo.z, wlo.w, b0, b1);
                mma16816(C1[nt][0], C1[nt][1], C1[nt][2], C1[nt][3],
                         whi.x, whi.y, whi.z, whi.w, b0, b1);
            }
        }
#pragma unroll
        for (int nt = 0; nt < NT1; ++nt) {
            int bc = nt * 8 + 2 * tg;
            float2 a0 = make_float2(sigm(C0[nt][0]), sigm(C0[nt][1]));
            float2 a1 = make_float2(sigm(C0[nt][2]), sigm(C0[nt][3]));
            float2 b0, b1;
            if (loB_tanh) {
                b0 = make_float2(tanha(C1[nt][0]), tanha(C1[nt][1]));
                b1 = make_float2(tanha(C1[nt][2]), tanha(C1[nt][3]));
            } else {
                b0 = make_float2(sigm(C1[nt][0]), sigm(C1[nt][1]));
                b1 = make_float2(sigm(C1[nt][2]), sigm(C1[nt][3]));
            }
            *(float2*)&gA[jb * G_STR + bc]       = a0;
            *(float2*)&gA[(jb + 8) * G_STR + bc] = a1;
            *(float2*)&gB[jb * G_STR + bc]       = b0;
            *(float2*)&gB[(jb + 8) * G_STR + bc] = b1;
        }
        __syncthreads();
#pragma unroll
        for (int i = 0; i < 4; ++i) {
            int kp = pb_kp0 + 16 * i;
            int j0 = 2 * kp, j1 = j0 + 1;
            float i0 = gi[j0 * G_STR + pb_b], i1 = gi[j1 * G_STR + pb_b];
            float f0 = gf[j0 * G_STR + pb_b], f1 = gf[j1 * G_STR + pb_b];
            float g0 = gg[j0 * G_STR + pb_b], g1 = gg[j1 * G_STR + pb_b];
            float o0 = go[j0 * G_STR + pb_b], o1 = go[j1 * G_STR + pb_b];
            cr[2 * i]     = fmaf(f0, cr[2 * i],     i0 * g0);
            cr[2 * i + 1] = fmaf(f1, cr[2 * i + 1], i1 * g1);
            float h0 = o0 * tanha(cr[2 * i]);
            float h1 = o1 * tanha(cr[2 * i + 1]);
            hnext[kp * H2_STR + pb_b] = bfpack(h0, h1);
            if (t == 139) {
                d_h1[(base + pb_b) * 128 + j0] = h0;
                d_h1[(base + pb_b) * 128 + j1] = h1;
            }
        }
        __syncthreads();
        u32* tmp = hcur; hcur = hnext; hnext = tmp;
    }
}

// ---------------------------------------------------------------------------
// K2: e2 input projection into K3-permuted layout
// ---------------------------------------------------------------------------
__global__ __launch_bounds__(256, 1) void k2_proj() {
    __shared__ float hsm[32 * 128];
    const int g = threadIdx.x;
    const int t0 = blockIdx.x * 32;
    for (int i = g; i < 32 * 128; i += 256) hsm[i] = d_h1[t0 * 128 + i];
    __syncthreads();
    float acc[32];
#pragma unroll
    for (int r = 0; r < 32; ++r) acc[r] = 0.f;
    for (int k = 0; k < 128; ++k) {
        float w = d_WihT_e2[k * 256 + g];
#pragma unroll
        for (int r = 0; r < 32; ++r) acc[r] = fmaf(hsm[r * 128 + k], w, acc[r]);
    }
    float b = d_bias_e2[g];
    int q = g >> 6, j = g & 63;
    int q2 = q & 1, slot = q >> 1;
    int tid2 = (j >> 4) * 32 + (q2 << 4) + (j & 15);
    int dst = tid2 * 2 + slot;
#pragma unroll
    for (int r = 0; r < 32; ++r) d_pre2[(t0 + r) * 256 + dst] = acc[r] + b;
}

// ---------------------------------------------------------------------------
// K3: e2 serial scan. 1 block, 128 threads, 4096 steps, H=64.
// v2.u64 (16B) h loads halve LDS count; pre prefetched 2 ahead + seeded.
// ---------------------------------------------------------------------------
__global__ __launch_bounds__(128, 1) void k3_e2(const float* __restrict__ Whh_e2) {
    __shared__ __align__(16) float h_sh[2][64];
    const int tid = threadIdx.x;
    const int w = tid >> 5, l = tid & 31;
    const int j = w * 16 + (l & 15);
    const int q2 = l >> 4;
    const int r0 = q2 ? (64 + j) : j;
    const int r1 = q2 ? (192 + j) : (128 + j);

    u64 w0[32], w1[32];
    const u64* W2 = (const u64*)Whh_e2;
#pragma unroll
    for (int k = 0; k < 32; ++k) { w0[k] = W2[r0 * 32 + k]; w1[k] = W2[r1 * 32 + k]; }

    if (tid < 64) h_sh[0][tid] = 0.f;
    float c = 0.f;
    const u64* preb = (const u64*)d_pre2;
    u64 p0 = preb[tid];
    u64 p1 = preb[128 + tid];
    __syncthreads();

    for (int t = 0; t < 4096; ++t) {
        u64 p2 = (t < 4094) ? preb[(t + 2) * 128 + tid] : 0ull;
        const ulonglong2* hp2 = (const ulonglong2*)h_sh[t & 1 ? 1 : 0];
        float2 pc = unpk(p0);
        u64 a00 = pack2(pc.x, 0.f), a01 = 0, a02 = 0, a03 = 0;
        u64 a10 = pack2(pc.y, 0.f), a11 = 0, a12 = 0, a13 = 0;
#pragma unroll
        for (int k = 0; k < 16; k += 2) {
            ulonglong2 ha = hp2[k];
            ulonglong2 hb = hp2[k + 1];
            a00 = ffma2u(w0[2 * k],     ha.x, a00);
            a01 = ffma2u(w0[2 * k + 1], ha.y, a01);
            a02 = ffma2u(w0[2 * k + 2], hb.x, a02);
            a03 = ffma2u(w0[2 * k + 3], hb.y, a03);
            a10 = ffma2u(w1[2 * k],     ha.x, a10);
            a11 = ffma2u(w1[2 * k + 1], ha.y, a11);
            a12 = ffma2u(w1[2 * k + 2], hb.x, a12);
            a13 = ffma2u(w1[2 * k + 3], hb.y, a13);
        }
        a00 = add2(add2(a00, a01), add2(a02, a03));
        a10 = add2(add2(a10, a11), add2(a12, a13));
        float2 v0 = unpk(a00), v1 = unpk(a10);
        float s0 = v0.x + v0.y;
        float s1 = v1.x + v1.y;
        float act0 = sigm(s0);
        float act1 = q2 ? sigm(s1) : tanha(s1);
        float o0 = __shfl_xor_sync(0xffffffffu, act0, 16);
        float o1 = __shfl_xor_sync(0xffffffffu, act1, 16);
        float iv = q2 ? o0 : act0;
        float fv = q2 ? act0 : o0;
        float gv = q2 ? o1 : act1;
        float ov = q2 ? act1 : o1;
        c = fmaf(fv, c, iv * gv);
        float h = ov * tanha(c);
        if (q2 == 0) h_sh[(t & 1) ^ 1][j] = h;
        __syncthreads();
        p0 = p1; p1 = p2;
    }
    if (tid < 64) d_zvec[tid] = h_sh[0][tid];
}

// ---------------------------------------------------------------------------
// K4: decoder (d1 H=128 + fused d2 H=1). 1 block, 512 threads, 140 steps.
// fp32 weights streamed from d_WT4_d1 (R12-passing version).
// ---------------------------------------------------------------------------
__global__ __launch_bounds__(512, 1) void k4_dec(const float* __restrict__ Wih_d1,
                                                 const float* __restrict__ Wih_d2,
                                                 const float* __restrict__ Whh_d2,
                                                 const float* __restrict__ bih_d2,
                                                 const float* __restrict__ bhh_d2,
                                                 float* __restrict__ out) {
    __shared__ float zsh[64];
    __shared__ float h_sh[128];
    __shared__ float gsh[512];
    const int g = threadIdx.x;
    if (g < 64)  zsh[g] = d_zvec[g];
    if (g < 128) h_sh[g] = 0.f;
    __syncthreads();
    float wz = d_bias_d1[g];
#pragma unroll 8
    for (int k = 0; k < 64; ++k) wz = fmaf(Wih_d1[g * 64 + k], zsh[k], wz);
    const bool is_t = (g >= 256 && g < 384);
    float c = 0.f;

    float wd2[16], b2[4], wh[4];
    float c2 = 0.f, h2 = 0.f;
    if (g < 32) {
#pragma unroll
        for (int q = 0; q < 4; ++q) {
#pragma unroll
            for (int m = 0; m < 4; ++m) wd2[q * 4 + m] = Wih_d2[q * 128 + m * 32 + g];
            b2[q] = bih_d2[q] + bhh_d2[q];
            wh[q] = Whh_d2[q];
        }
    }
    const float4* __restrict__ Wp = d_WT4_d1 + g;
    const u64* hs2 = (const u64*)h_sh;

    for (int t = 0; t < 140; ++t) {
        u64 a0 = 0, a1 = 0;
#pragma unroll 8
        for (int k4 = 0; k4 < 32; ++k4) {
            float4 w = Wp[(size_t)k4 * 512];
            a0 = ffma2u(pack2(w.x, w.y), hs2[2 * k4], a0);
            a1 = ffma2u(pack2(w.z, w.w), hs2[2 * k4 + 1], a1);
        }
        a0 = add2(a0, a1);
        float2 v = unpk(a0);
        float xv = v.x + v.y + wz;
        gsh[g] = is_t ? tanha(xv) : sigm(xv);
        __syncthreads();
        if (g < 128) {
            float iv = gsh[g], fv = gsh[128 + g], gv = gsh[256 + g], ov = gsh[384 + g];
            c = fmaf(fv, c, iv * gv);
            h_sh[g] = ov * tanha(c);
        }
        __syncthreads();
        if (g < 32) {
            float p0 = 0.f, p1 = 0.f, p2 = 0.f, p3 = 0.f;
#pragma unroll
            for (int m = 0; m < 4; ++m) {
                float hv = h_sh[m * 32 + g];
                p0 = fmaf(wd2[0 * 4 + m], hv, p0);
                p1 = fmaf(wd2[1 * 4 + m], hv, p1);
                p2 = fmaf(wd2[2 * 4 + m], hv, p2);
                p3 = fmaf(wd2[3 * 4 + m], hv, p3);
            }
#pragma unroll
            for (int off = 16; off > 0; off >>= 1) {
                p0 += __shfl_xor_sync(0xffffffffu, p0, off);
                p1 += __shfl_xor_sync(0xffffffffu, p1, off);
                p2 += __shfl_xor_sync(0xffffffffu, p2, off);
                p3 += __shfl_xor_sync(0xffffffffu, p3, off);
            }
            float iv2 = sigm(p0 + b2[0] + wh[0] * h2);
            float fv2 = sigm(p1 + b2[1] + wh[1] * h2);
            float gv2 = tanha(p2 + b2[2] + wh[2] * h2);
            float ov2 = sigm(p3 + b2[3] + wh[3] * h2);
            c2 = fmaf(fv2, c2, iv2 * gv2);
            h2 = ov2 * tanha(c2);
            if (g == 0) out[t] = h2;
        }
    }
}

// ---------------------------------------------------------------------------
// Launch
// ---------------------------------------------------------------------------
extern "C" void kernel_launch(void* const* d_in, const int* in_sizes, int n_in,
                              void* d_out, int out_size) {
    const float* x      = (const float*)d_in[0];
    const float* Wih_e1 = (const float*)d_in[1];
    const float* Whh_e1 = (const float*)d_in[2];
    const float* bih_e1 = (const float*)d_in[3];
    const float* bhh_e1 = (const float*)d_in[4];
    const float* Wih_e2 = (const float*)d_in[5];
    const float* Whh_e2 = (const float*)d_in[6];
    const float* bih_e2 = (const float*)d_in[7];
    const float* bhh_e2 = (const float*)d_in[8];
    const float* Wih_d1 = (const float*)d_in[9];
    const float* Whh_d1 = (const float*)d_in[10];
    const float* bih_d1 = (const float*)d_in[11];
    const float* bhh_d1 = (const float*)d_in[12];
    const float* Wih_d2 = (const float*)d_in[13];
    const float* Whh_d2 = (const float*)d_in[14];
    const float* bih_d2 = (const float*)d_in[15];
    const float* bhh_d2 = (const float*)d_in[16];
    float* out = (float*)d_out;
    (void)in_sizes; (void)n_in; (void)out_size;

    cudaFuncSetAttribute(k1_e1, cudaFuncAttributeMaxDynamicSharedMemorySize, K1_SMEM);

    k0_prep<<<64, 256>>>(Whh_e1, bih_e1, bhh_e1, Wih_e2, bih_e2, bhh_e2,
                         Whh_d1, bih_d1, bhh_d1);
    k1_e1<<<128, 512, K1_SMEM>>>(x, Wih_e1);
    k2_proj<<<128, 256>>>();
    k3_e2<<<1, 128>>>(Whh_e2);
    k4_dec<<<1, 512>>>(Wih_d1, Wih_d2, Whh_d2, bih_d2, bhh_d2, out);
}